// round 6
// baseline (speedup 1.0000x reference)
#include <cuda_runtime.h>

#define N_HID 64
#define MAXN 100000
#define MAXE 3200000
#define NGRAPH 512
#define SCAN_BLK 1024
#define MAXPART 128

// Scratch (device globals — no allocation allowed; zero-initialized at load)
__device__ __align__(16) float g_dinv[MAXN];
__device__ __align__(16) int   g_cnt2[MAXN];        // zero at entry of each call (scan1 re-zeroes)
__device__ __align__(16) int   g_off[MAXN + 1];
__device__ __align__(16) int   g_cur[MAXN];         // running write cursor (starts at g_off[i])
__device__ __align__(16) int   g_part[MAXPART];
__device__ __align__(16) int2  g_elist[MAXE + 8];   // (src, w-bits fp32)
__device__ __align__(16) float g_A[(size_t)MAXN * N_HID];
__device__ __align__(16) float g_B[(size_t)MAXN * N_HID];
__device__ __align__(16) float g_pool[NGRAPH * N_HID];
__device__ float g_cnt[NGRAPH];

// ---------------- histogram of dst (int4 loads) ----------------
__global__ void k_hist(const int* __restrict__ dst, int E) {
    int e4 = (blockIdx.x * blockDim.x + threadIdx.x) * 4;
    if (e4 + 3 < E) {
        int4 d = *(const int4*)(dst + e4);
        atomicAdd(&g_cnt2[d.x], 1);
        atomicAdd(&g_cnt2[d.y], 1);
        atomicAdd(&g_cnt2[d.z], 1);
        atomicAdd(&g_cnt2[d.w], 1);
    } else {
        for (int e = e4; e < E; e++) atomicAdd(&g_cnt2[dst[e]], 1);
    }
}

// ---------------- block scan (reads AND re-zeroes g_cnt2; derives dinv) ----------------
__global__ void __launch_bounds__(256) k_scan1(int n) {
    __shared__ int wt[8];
    __shared__ int wtex[8];
    const int t = threadIdx.x, lane = t & 31, warp = t >> 5;
    const int base = blockIdx.x * SCAN_BLK + t * 4;
    int a0 = (base + 0 < n) ? g_cnt2[base + 0] : 0;
    int a1 = (base + 1 < n) ? g_cnt2[base + 1] : 0;
    int a2 = (base + 2 < n) ? g_cnt2[base + 2] : 0;
    int a3 = (base + 3 < n) ? g_cnt2[base + 3] : 0;
    int sum4 = a0 + a1 + a2 + a3;
    int v = sum4;
#pragma unroll
    for (int o = 1; o < 32; o <<= 1) {
        int u = __shfl_up_sync(0xFFFFFFFFu, v, o);
        if (lane >= o) v += u;
    }
    if (lane == 31) wt[warp] = v;
    __syncthreads();
    if (t == 0) {
        int run = 0;
#pragma unroll
        for (int w = 0; w < 8; w++) { wtex[w] = run; run += wt[w]; }
        g_part[blockIdx.x] = run;
    }
    __syncthreads();
    int ex = v - sum4 + wtex[warp];
    if (base + 0 < n) { g_off[base + 0] = ex;                g_dinv[base + 0] = rsqrtf((float)a0 + 1.0f); g_cnt2[base + 0] = 0; }
    if (base + 1 < n) { g_off[base + 1] = ex + a0;           g_dinv[base + 1] = rsqrtf((float)a1 + 1.0f); g_cnt2[base + 1] = 0; }
    if (base + 2 < n) { g_off[base + 2] = ex + a0 + a1;      g_dinv[base + 2] = rsqrtf((float)a2 + 1.0f); g_cnt2[base + 2] = 0; }
    if (base + 3 < n) { g_off[base + 3] = ex + a0 + a1 + a2; g_dinv[base + 3] = rsqrtf((float)a3 + 1.0f); g_cnt2[base + 3] = 0; }
}

// ---------------- scan finalize: add block prefix; g_cur = g_off; zero pool ----------------
__global__ void __launch_bounds__(256) k_scan3(int n, int E, int nb) {
    __shared__ int sp[MAXPART];
    int t = threadIdx.x;
    if (t < MAXPART) sp[t] = (t < nb) ? g_part[t] : 0;
    __syncthreads();
    if (t == 0) {
        int run = 0;
        for (int i = 0; i < nb; i++) { int c = sp[i]; sp[i] = run; run += c; }
    }
    __syncthreads();
    int i = blockIdx.x * blockDim.x + t;
    if (i < n) {
        int o = g_off[i] + sp[i >> 10];
        g_off[i] = o;
        g_cur[i] = o;
    }
    if (i == 0) g_off[n] = E;
    if (i < NGRAPH * N_HID) g_pool[i] = 0.0f;
    if (i < NGRAPH) g_cnt[i] = 0.0f;
}

// ---------------- counting-sort edges by dst (cursor IS the slot) ----------------
__global__ void k_sortscatter(const int* __restrict__ src, const int* __restrict__ dst, int E) {
    int e4 = (blockIdx.x * blockDim.x + threadIdx.x) * 4;
    if (e4 + 3 < E) {
        int4 s = *(const int4*)(src + e4);
        int4 d = *(const int4*)(dst + e4);
        {
            float w = g_dinv[s.x] * g_dinv[d.x];
            int r = atomicAdd(&g_cur[d.x], 1);
            g_elist[r] = make_int2(s.x, __float_as_int(w));
        }
        {
            float w = g_dinv[s.y] * g_dinv[d.y];
            int r = atomicAdd(&g_cur[d.y], 1);
            g_elist[r] = make_int2(s.y, __float_as_int(w));
        }
        {
            float w = g_dinv[s.z] * g_dinv[d.z];
            int r = atomicAdd(&g_cur[d.z], 1);
            g_elist[r] = make_int2(s.z, __float_as_int(w));
        }
        {
            float w = g_dinv[s.w] * g_dinv[d.w];
            int r = atomicAdd(&g_cur[d.w], 1);
            g_elist[r] = make_int2(s.w, __float_as_int(w));
        }
    } else {
        for (int e = e4; e < E; e++) {
            int s = src[e], d = dst[e];
            float w = g_dinv[s] * g_dinv[d];
            int r = atomicAdd(&g_cur[d], 1);
            g_elist[r] = make_int2(s, __float_as_int(w));
        }
    }
}

// ---------------- GEMM: H[n][64] = act(X[n][K]) @ W[K][64] ----------------
template <int K, bool PRE>
__global__ void __launch_bounds__(256) k_gemm(const float* __restrict__ X,
                                              const float* __restrict__ W,
                                              const float* __restrict__ pb,
                                              float* __restrict__ H, int n) {
    __shared__ float Ws[64][64];
    __shared__ float Xs[64][64];
    const int row0 = blockIdx.x * 64;
    const int tx = threadIdx.x & 15;
    const int ty = threadIdx.x >> 4;
    float acc[4][4] = {};

    for (int k0 = 0; k0 < K; k0 += 64) {
        for (int i = threadIdx.x; i < 64 * 64; i += 256) {
            int k = i >> 6, c = i & 63;
            Ws[k][c] = W[(size_t)(k0 + k) * 64 + c];
        }
        for (int i = threadIdx.x; i < 64 * 64; i += 256) {
            int r = i >> 6, k = i & 63;
            int row = row0 + r;
            float v = 0.0f;
            if (row < n) {
                v = X[(size_t)row * K + k0 + k];
                if (PRE) v = fmaxf(v + pb[k0 + k], 0.0f);
            }
            Xs[r][k] = v;
        }
        __syncthreads();
#pragma unroll
        for (int k = 0; k < 64; k++) {
            float4 wv = *(const float4*)&Ws[k][tx * 4];
            float x0 = Xs[ty * 4 + 0][k];
            float x1 = Xs[ty * 4 + 1][k];
            float x2 = Xs[ty * 4 + 2][k];
            float x3 = Xs[ty * 4 + 3][k];
            acc[0][0] += x0 * wv.x; acc[0][1] += x0 * wv.y; acc[0][2] += x0 * wv.z; acc[0][3] += x0 * wv.w;
            acc[1][0] += x1 * wv.x; acc[1][1] += x1 * wv.y; acc[1][2] += x1 * wv.z; acc[1][3] += x1 * wv.w;
            acc[2][0] += x2 * wv.x; acc[2][1] += x2 * wv.y; acc[2][2] += x2 * wv.z; acc[2][3] += x2 * wv.w;
            acc[3][0] += x3 * wv.x; acc[3][1] += x3 * wv.y; acc[3][2] += x3 * wv.z; acc[3][3] += x3 * wv.w;
        }
        __syncthreads();
    }
#pragma unroll
    for (int i = 0; i < 4; i++) {
        int row = row0 + ty * 4 + i;
        if (row < n) {
            float4 o = make_float4(acc[i][0], acc[i][1], acc[i][2], acc[i][3]);
            *(float4*)&H[(size_t)row * 64 + tx * 4] = o;
        }
    }
}

// ---------------- gather v3: warp/node, float4 lanes, 2 edges per row-LDG ----------------
// 16 lanes cover one 256B row; grp = lane>>4 picks which of 2 edges per int4 elist load.
__global__ void __launch_bounds__(256) k_gather(const float* __restrict__ Ain,
                                                float* __restrict__ Hout, int n) {
    int wid = (blockIdx.x * blockDim.x + threadIdx.x) >> 5;
    if (wid >= n) return;
    const int lane = threadIdx.x & 31;
    const int grp = lane >> 4;        // 0 or 1
    const int fo = (lane & 15) * 4;   // feature offset (float4)
    const int beg = g_off[wid];
    const int end = g_off[wid + 1];

    float4 acc = make_float4(0.f, 0.f, 0.f, 0.f);
    int j = beg;

    // peel one edge if beg is odd (keeps int4 loads 16B-aligned); only grp 0 counts it
    if ((j & 1) && j < end) {
        int2 p = g_elist[j];
        if (grp == 0) {
            float w = __int_as_float(p.y);
            float4 v = *(const float4*)(Ain + (size_t)p.x * 64 + fo);
            acc.x += w * v.x; acc.y += w * v.y; acc.z += w * v.z; acc.w += w * v.w;
        }
        j++;
    }

    // 8 edges per iteration: 4 elist int4 (broadcast) + 4 row float4 loads in flight
    for (; j + 8 <= end; j += 8) {
        int4 q0 = *(const int4*)&g_elist[j + 0];
        int4 q1 = *(const int4*)&g_elist[j + 2];
        int4 q2 = *(const int4*)&g_elist[j + 4];
        int4 q3 = *(const int4*)&g_elist[j + 6];
        int s0 = grp ? q0.z : q0.x;  float w0 = __int_as_float(grp ? q0.w : q0.y);
        int s1 = grp ? q1.z : q1.x;  float w1 = __int_as_float(grp ? q1.w : q1.y);
        int s2 = grp ? q2.z : q2.x;  float w2 = __int_as_float(grp ? q2.w : q2.y);
        int s3 = grp ? q3.z : q3.x;  float w3 = __int_as_float(grp ? q3.w : q3.y);
        float4 v0 = *(const float4*)(Ain + (size_t)s0 * 64 + fo);
        float4 v1 = *(const float4*)(Ain + (size_t)s1 * 64 + fo);
        float4 v2 = *(const float4*)(Ain + (size_t)s2 * 64 + fo);
        float4 v3 = *(const float4*)(Ain + (size_t)s3 * 64 + fo);
        acc.x += w0 * v0.x; acc.y += w0 * v0.y; acc.z += w0 * v0.z; acc.w += w0 * v0.w;
        acc.x += w1 * v1.x; acc.y += w1 * v1.y; acc.z += w1 * v1.z; acc.w += w1 * v1.w;
        acc.x += w2 * v2.x; acc.y += w2 * v2.y; acc.z += w2 * v2.z; acc.w += w2 * v2.w;
        acc.x += w3 * v3.x; acc.y += w3 * v3.y; acc.z += w3 * v3.z; acc.w += w3 * v3.w;
    }
    // tail pairs
    for (; j + 2 <= end; j += 2) {
        int4 q = *(const int4*)&g_elist[j];
        int s = grp ? q.z : q.x;
        float w = __int_as_float(grp ? q.w : q.y);
        float4 v = *(const float4*)(Ain + (size_t)s * 64 + fo);
        acc.x += w * v.x; acc.y += w * v.y; acc.z += w * v.z; acc.w += w * v.w;
    }
    // last single edge (grp 0 only)
    if (j < end && grp == 0) {
        int2 p = g_elist[j];
        float w = __int_as_float(p.y);
        float4 v = *(const float4*)(Ain + (size_t)p.x * 64 + fo);
        acc.x += w * v.x; acc.y += w * v.y; acc.z += w * v.z; acc.w += w * v.w;
    }

    // combine the two edge-groups
    acc.x += __shfl_down_sync(0xFFFFFFFFu, acc.x, 16);
    acc.y += __shfl_down_sync(0xFFFFFFFFu, acc.y, 16);
    acc.z += __shfl_down_sync(0xFFFFFFFFu, acc.z, 16);
    acc.w += __shfl_down_sync(0xFFFFFFFFu, acc.w, 16);

    if (lane < 16) {
        float dv = g_dinv[wid];
        float sc = dv * dv;
        float4 a = *(const float4*)(Ain + (size_t)wid * 64 + fo);
        acc.x += sc * a.x; acc.y += sc * a.y; acc.z += sc * a.z; acc.w += sc * a.w;
        *(float4*)(Hout + (size_t)wid * 64 + fo) = acc;
    }
}

// ---------------- pooling ----------------
__device__ __forceinline__ void red_add_v4(float* p, float a, float b, float c, float d) {
    unsigned long long gp;
    asm("cvta.to.global.u64 %0, %1;" : "=l"(gp) : "l"(p));
    asm volatile("red.global.add.v4.f32 [%0], {%1, %2, %3, %4};"
                 :: "l"(gp), "f"(a), "f"(b), "f"(c), "f"(d) : "memory");
}

__global__ void k_pool(const float* __restrict__ H, const float* __restrict__ b3,
                       const int* __restrict__ batch, int n) {
    int idx = blockIdx.x * blockDim.x + threadIdx.x;
    int i = idx >> 4, c = idx & 15;
    if (i >= n) return;
    int g = batch[i];
    float4 h = *(const float4*)&H[(size_t)i * 64 + c * 4];
    float4 bb = *(const float4*)&b3[c * 4];
    h.x = fmaxf(h.x + bb.x, 0.0f);
    h.y = fmaxf(h.y + bb.y, 0.0f);
    h.z = fmaxf(h.z + bb.z, 0.0f);
    h.w = fmaxf(h.w + bb.w, 0.0f);
    red_add_v4(&g_pool[g * 64 + c * 4], h.x, h.y, h.z, h.w);
    if (c == 0) atomicAdd(&g_cnt[g], 1.0f);
}

// ---------------- classifier head ----------------
__global__ void k_classifier(const float* __restrict__ Wc1, const float* __restrict__ bc1,
                             const float* __restrict__ Wc2, const float* __restrict__ bc2,
                             float* __restrict__ out) {
    __shared__ float p[64];
    __shared__ float z[32];
    int g = blockIdx.x;
    int t = threadIdx.x;  // 32 threads
    float inv = 1.0f / fmaxf(g_cnt[g], 1.0f);
    p[t] = g_pool[g * 64 + t] * inv;
    p[t + 32] = g_pool[g * 64 + 32 + t] * inv;
    __syncwarp();
    float acc = bc1[t];
#pragma unroll
    for (int k = 0; k < 64; k++) acc += p[k] * Wc1[k * 32 + t];
    z[t] = fmaxf(acc, 0.0f);
    __syncwarp();
    if (t < 10) {
        float a = bc2[t];
#pragma unroll
        for (int k = 0; k < 32; k++) a += z[k] * Wc2[k * 10 + t];
        out[g * 10 + t] = a;
    }
}

extern "C" void kernel_launch(void* const* d_in, const int* in_sizes, int n_in,
                              void* d_out, int out_size) {
    const float* x    = (const float*)d_in[0];
    const int*   ei   = (const int*)d_in[1];
    const int*   bat  = (const int*)d_in[2];
    const float* W1   = (const float*)d_in[3];
    const float* b1   = (const float*)d_in[4];
    const float* W2   = (const float*)d_in[5];
    const float* b2   = (const float*)d_in[6];
    const float* W3   = (const float*)d_in[7];
    const float* b3   = (const float*)d_in[8];
    const float* Wc1  = (const float*)d_in[9];
    const float* bc1  = (const float*)d_in[10];
    const float* Wc2  = (const float*)d_in[11];
    const float* bc2  = (const float*)d_in[12];

    const int n = in_sizes[0] / 128;
    const int E = in_sizes[1] / 2;
    const int* src = ei;
    const int* dst = ei + E;

    float *dA, *dB;
    cudaGetSymbolAddress((void**)&dA, g_A);
    cudaGetSymbolAddress((void**)&dB, g_B);

    const int TB = 256;
    int gn   = (n + TB - 1) / TB;
    int gE4  = (E + 4 * TB - 1) / (4 * TB);
    int gn16 = (int)(((long long)n * 16 + TB - 1) / TB);
    int gW   = (int)(((long long)n * 32 + TB - 1) / TB);
    int gRow = (n + 63) / 64;
    int nb   = (n + SCAN_BLK - 1) / SCAN_BLK;

    // ---- CSR build ----
    k_hist<<<gE4, TB>>>(dst, E);                      // launch 1
    k_scan1<<<nb, 256>>>(n);                          // launch 2
    k_scan3<<<gn, TB>>>(n, E, nb);                    // launch 3
    k_sortscatter<<<gE4, TB>>>(src, dst, E);          // launch 4  <- profiled

    // layer 1
    k_gemm<128, false><<<gRow, TB>>>(x, W1, nullptr, dA, n);
    k_gather<<<gW, TB>>>(dA, dB, n);

    // layer 2
    k_gemm<64, true><<<gRow, TB>>>(dB, W2, b1, dA, n);
    k_gather<<<gW, TB>>>(dA, dB, n);

    // layer 3
    k_gemm<64, true><<<gRow, TB>>>(dB, W3, b2, dA, n);
    k_gather<<<gW, TB>>>(dA, dB, n);

    // mean-pool (fuses relu(B + b3)) + classifier
    k_pool<<<gn16, TB>>>(dB, b3, bat, n);
    k_classifier<<<NGRAPH, 32>>>(Wc1, bc1, Wc2, bc2, (float*)d_out);
}

// round 7
// speedup vs baseline: 1.1683x; 1.1683x over previous
#include <cuda_runtime.h>
#include <cuda_fp16.h>

#define N_HID 64
#define MAXN 100000
#define MAXE 3200000
#define NGRAPH 512
#define SCAN_BLK 1024
#define MAXPART 128

// Scratch (device globals — no allocation allowed; zero-initialized at load)
__device__ __align__(16) float  g_dinv[MAXN];
__device__ __align__(16) int    g_cnt2[MAXN];        // zero at entry (scan1 re-zeroes)
__device__ __align__(16) int    g_off[MAXN + 1];
__device__ __align__(16) int    g_cur[MAXN];         // write cursor (starts at g_off[i])
__device__ __align__(16) int    g_part[MAXPART];
__device__ __align__(16) int    g_esrc[MAXE + 8];    // sorted src indices (4B/edge, no weights!)
__device__ __align__(16) __half g_A16[(size_t)MAXN * N_HID];  // A' = dinv[row] * h[row], fp16
__device__ __align__(16) float  g_B[(size_t)MAXN * N_HID];    // aggregated fp32
__device__ __align__(16) float  g_pool[NGRAPH * N_HID];
__device__ float g_cnt[NGRAPH];

// ---------------- histogram of dst (int4 loads) ----------------
__global__ void k_hist(const int* __restrict__ dst, int E) {
    int e4 = (blockIdx.x * blockDim.x + threadIdx.x) * 4;
    if (e4 + 3 < E) {
        int4 d = *(const int4*)(dst + e4);
        atomicAdd(&g_cnt2[d.x], 1);
        atomicAdd(&g_cnt2[d.y], 1);
        atomicAdd(&g_cnt2[d.z], 1);
        atomicAdd(&g_cnt2[d.w], 1);
    } else {
        for (int e = e4; e < E; e++) atomicAdd(&g_cnt2[dst[e]], 1);
    }
}

// ---------------- block scan (reads AND re-zeroes g_cnt2; derives dinv) ----------------
__global__ void __launch_bounds__(256) k_scan1(int n) {
    __shared__ int wt[8];
    __shared__ int wtex[8];
    const int t = threadIdx.x, lane = t & 31, warp = t >> 5;
    const int base = blockIdx.x * SCAN_BLK + t * 4;
    int a0 = (base + 0 < n) ? g_cnt2[base + 0] : 0;
    int a1 = (base + 1 < n) ? g_cnt2[base + 1] : 0;
    int a2 = (base + 2 < n) ? g_cnt2[base + 2] : 0;
    int a3 = (base + 3 < n) ? g_cnt2[base + 3] : 0;
    int sum4 = a0 + a1 + a2 + a3;
    int v = sum4;
#pragma unroll
    for (int o = 1; o < 32; o <<= 1) {
        int u = __shfl_up_sync(0xFFFFFFFFu, v, o);
        if (lane >= o) v += u;
    }
    if (lane == 31) wt[warp] = v;
    __syncthreads();
    if (t == 0) {
        int run = 0;
#pragma unroll
        for (int w = 0; w < 8; w++) { wtex[w] = run; run += wt[w]; }
        g_part[blockIdx.x] = run;
    }
    __syncthreads();
    int ex = v - sum4 + wtex[warp];
    if (base + 0 < n) { g_off[base + 0] = ex;                g_dinv[base + 0] = rsqrtf((float)a0 + 1.0f); g_cnt2[base + 0] = 0; }
    if (base + 1 < n) { g_off[base + 1] = ex + a0;           g_dinv[base + 1] = rsqrtf((float)a1 + 1.0f); g_cnt2[base + 1] = 0; }
    if (base + 2 < n) { g_off[base + 2] = ex + a0 + a1;      g_dinv[base + 2] = rsqrtf((float)a2 + 1.0f); g_cnt2[base + 2] = 0; }
    if (base + 3 < n) { g_off[base + 3] = ex + a0 + a1 + a2; g_dinv[base + 3] = rsqrtf((float)a3 + 1.0f); g_cnt2[base + 3] = 0; }
}

// ---------------- scan finalize: add block prefix; g_cur = g_off; zero pool ----------------
__global__ void __launch_bounds__(256) k_scan3(int n, int E, int nb) {
    __shared__ int sp[MAXPART];
    int t = threadIdx.x;
    if (t < MAXPART) sp[t] = (t < nb) ? g_part[t] : 0;
    __syncthreads();
    if (t == 0) {
        int run = 0;
        for (int i = 0; i < nb; i++) { int c = sp[i]; sp[i] = run; run += c; }
    }
    __syncthreads();
    int i = blockIdx.x * blockDim.x + t;
    if (i < n) {
        int o = g_off[i] + sp[i >> 10];
        g_off[i] = o;
        g_cur[i] = o;
    }
    if (i == 0) g_off[n] = E;
    if (i < NGRAPH * N_HID) g_pool[i] = 0.0f;
    if (i < NGRAPH) g_cnt[i] = 0.0f;
}

// ---------------- counting-sort by dst: store ONLY src (no weight, no dinv loads) ----------------
__global__ void k_sortscatter(const int* __restrict__ src, const int* __restrict__ dst, int E) {
    int e4 = (blockIdx.x * blockDim.x + threadIdx.x) * 4;
    if (e4 + 3 < E) {
        int4 s = *(const int4*)(src + e4);
        int4 d = *(const int4*)(dst + e4);
        { int r = atomicAdd(&g_cur[d.x], 1); g_esrc[r] = s.x; }
        { int r = atomicAdd(&g_cur[d.y], 1); g_esrc[r] = s.y; }
        { int r = atomicAdd(&g_cur[d.z], 1); g_esrc[r] = s.z; }
        { int r = atomicAdd(&g_cur[d.w], 1); g_esrc[r] = s.w; }
    } else {
        for (int e = e4; e < E; e++) {
            int r = atomicAdd(&g_cur[dst[e]], 1);
            g_esrc[r] = src[e];
        }
    }
}

// ---------------- GEMM: A16[n][64] = dinv[row] * (act(X[n][K]) @ W[K][64]), fp16 out ----------------
template <int K, bool PRE>
__global__ void __launch_bounds__(256) k_gemm(const float* __restrict__ X,
                                              const float* __restrict__ W,
                                              const float* __restrict__ pb,
                                              __half* __restrict__ H, int n) {
    __shared__ float Ws[64][64];
    __shared__ float Xs[64][64];
    const int row0 = blockIdx.x * 64;
    const int tx = threadIdx.x & 15;
    const int ty = threadIdx.x >> 4;
    float acc[4][4] = {};

    for (int k0 = 0; k0 < K; k0 += 64) {
        for (int i = threadIdx.x; i < 64 * 64; i += 256) {
            int k = i >> 6, c = i & 63;
            Ws[k][c] = W[(size_t)(k0 + k) * 64 + c];
        }
        for (int i = threadIdx.x; i < 64 * 64; i += 256) {
            int r = i >> 6, k = i & 63;
            int row = row0 + r;
            float v = 0.0f;
            if (row < n) {
                v = X[(size_t)row * K + k0 + k];
                if (PRE) v = fmaxf(v + pb[k0 + k], 0.0f);
            }
            Xs[r][k] = v;
        }
        __syncthreads();
#pragma unroll
        for (int k = 0; k < 64; k++) {
            float4 wv = *(const float4*)&Ws[k][tx * 4];
            float x0 = Xs[ty * 4 + 0][k];
            float x1 = Xs[ty * 4 + 1][k];
            float x2 = Xs[ty * 4 + 2][k];
            float x3 = Xs[ty * 4 + 3][k];
            acc[0][0] += x0 * wv.x; acc[0][1] += x0 * wv.y; acc[0][2] += x0 * wv.z; acc[0][3] += x0 * wv.w;
            acc[1][0] += x1 * wv.x; acc[1][1] += x1 * wv.y; acc[1][2] += x1 * wv.z; acc[1][3] += x1 * wv.w;
            acc[2][0] += x2 * wv.x; acc[2][1] += x2 * wv.y; acc[2][2] += x2 * wv.z; acc[2][3] += x2 * wv.w;
            acc[3][0] += x3 * wv.x; acc[3][1] += x3 * wv.y; acc[3][2] += x3 * wv.z; acc[3][3] += x3 * wv.w;
        }
        __syncthreads();
    }
#pragma unroll
    for (int i = 0; i < 4; i++) {
        int row = row0 + ty * 4 + i;
        if (row < n) {
            float dv = g_dinv[row];
            union { uint2 u; __half2 h[2]; } pk;
            pk.h[0] = __floats2half2_rn(acc[i][0] * dv, acc[i][1] * dv);
            pk.h[1] = __floats2half2_rn(acc[i][2] * dv, acc[i][3] * dv);
            *(uint2*)&H[(size_t)row * 64 + tx * 4] = pk.u;
        }
    }
}

// ---------------- gather: warp/node, lane = half2 column, no weights ----------------
// out[d] = dinv[d] * ( sum_j A'[src_j] + A'[d] )
__global__ void __launch_bounds__(256) k_gather(const __half* __restrict__ Ain,
                                                float* __restrict__ Hout, int n) {
    int wid = (blockIdx.x * blockDim.x + threadIdx.x) >> 5;
    if (wid >= n) return;
    const int lane = threadIdx.x & 31;
    const int beg = g_off[wid];
    const int end = g_off[wid + 1];
    const __half2* A = (const __half2*)Ain;

    // self term
    float2 acc = __half22float2(A[(size_t)wid * 32 + lane]);

    int j = beg;
    // peel to int4 (16B) alignment of g_esrc
    while ((j & 3) && j < end) {
        float2 v = __half22float2(A[(size_t)g_esrc[j] * 32 + lane]);
        acc.x += v.x; acc.y += v.y;
        j++;
    }
    // 8 edges per iteration: 2 broadcast int4 + 8 independent row LDG.32
    for (; j + 8 <= end; j += 8) {
        int4 q0 = *(const int4*)&g_esrc[j + 0];
        int4 q1 = *(const int4*)&g_esrc[j + 4];
        float2 v0 = __half22float2(A[(size_t)q0.x * 32 + lane]);
        float2 v1 = __half22float2(A[(size_t)q0.y * 32 + lane]);
        float2 v2 = __half22float2(A[(size_t)q0.z * 32 + lane]);
        float2 v3 = __half22float2(A[(size_t)q0.w * 32 + lane]);
        float2 v4 = __half22float2(A[(size_t)q1.x * 32 + lane]);
        float2 v5 = __half22float2(A[(size_t)q1.y * 32 + lane]);
        float2 v6 = __half22float2(A[(size_t)q1.z * 32 + lane]);
        float2 v7 = __half22float2(A[(size_t)q1.w * 32 + lane]);
        acc.x += v0.x; acc.y += v0.y;
        acc.x += v1.x; acc.y += v1.y;
        acc.x += v2.x; acc.y += v2.y;
        acc.x += v3.x; acc.y += v3.y;
        acc.x += v4.x; acc.y += v4.y;
        acc.x += v5.x; acc.y += v5.y;
        acc.x += v6.x; acc.y += v6.y;
        acc.x += v7.x; acc.y += v7.y;
    }
    for (; j + 4 <= end; j += 4) {
        int4 q = *(const int4*)&g_esrc[j];
        float2 v0 = __half22float2(A[(size_t)q.x * 32 + lane]);
        float2 v1 = __half22float2(A[(size_t)q.y * 32 + lane]);
        float2 v2 = __half22float2(A[(size_t)q.z * 32 + lane]);
        float2 v3 = __half22float2(A[(size_t)q.w * 32 + lane]);
        acc.x += v0.x; acc.y += v0.y;
        acc.x += v1.x; acc.y += v1.y;
        acc.x += v2.x; acc.y += v2.y;
        acc.x += v3.x; acc.y += v3.y;
    }
    for (; j < end; j++) {
        float2 v = __half22float2(A[(size_t)g_esrc[j] * 32 + lane]);
        acc.x += v.x; acc.y += v.y;
    }

    float dv = g_dinv[wid];
    float2 o = make_float2(acc.x * dv, acc.y * dv);
    *(float2*)(Hout + (size_t)wid * 64 + lane * 2) = o;
}

// ---------------- pooling ----------------
__device__ __forceinline__ void red_add_v4(float* p, float a, float b, float c, float d) {
    unsigned long long gp;
    asm("cvta.to.global.u64 %0, %1;" : "=l"(gp) : "l"(p));
    asm volatile("red.global.add.v4.f32 [%0], {%1, %2, %3, %4};"
                 :: "l"(gp), "f"(a), "f"(b), "f"(c), "f"(d) : "memory");
}

__global__ void k_pool(const float* __restrict__ H, const float* __restrict__ b3,
                       const int* __restrict__ batch, int n) {
    int idx = blockIdx.x * blockDim.x + threadIdx.x;
    int i = idx >> 4, c = idx & 15;
    if (i >= n) return;
    int g = batch[i];
    float4 h = *(const float4*)&H[(size_t)i * 64 + c * 4];
    float4 bb = *(const float4*)&b3[c * 4];
    h.x = fmaxf(h.x + bb.x, 0.0f);
    h.y = fmaxf(h.y + bb.y, 0.0f);
    h.z = fmaxf(h.z + bb.z, 0.0f);
    h.w = fmaxf(h.w + bb.w, 0.0f);
    red_add_v4(&g_pool[g * 64 + c * 4], h.x, h.y, h.z, h.w);
    if (c == 0) atomicAdd(&g_cnt[g], 1.0f);
}

// ---------------- classifier head ----------------
__global__ void k_classifier(const float* __restrict__ Wc1, const float* __restrict__ bc1,
                             const float* __restrict__ Wc2, const float* __restrict__ bc2,
                             float* __restrict__ out) {
    __shared__ float p[64];
    __shared__ float z[32];
    int g = blockIdx.x;
    int t = threadIdx.x;  // 32 threads
    float inv = 1.0f / fmaxf(g_cnt[g], 1.0f);
    p[t] = g_pool[g * 64 + t] * inv;
    p[t + 32] = g_pool[g * 64 + 32 + t] * inv;
    __syncwarp();
    float acc = bc1[t];
#pragma unroll
    for (int k = 0; k < 64; k++) acc += p[k] * Wc1[k * 32 + t];
    z[t] = fmaxf(acc, 0.0f);
    __syncwarp();
    if (t < 10) {
        float a = bc2[t];
#pragma unroll
        for (int k = 0; k < 32; k++) a += z[k] * Wc2[k * 10 + t];
        out[g * 10 + t] = a;
    }
}

extern "C" void kernel_launch(void* const* d_in, const int* in_sizes, int n_in,
                              void* d_out, int out_size) {
    const float* x    = (const float*)d_in[0];
    const int*   ei   = (const int*)d_in[1];
    const int*   bat  = (const int*)d_in[2];
    const float* W1   = (const float*)d_in[3];
    const float* b1   = (const float*)d_in[4];
    const float* W2   = (const float*)d_in[5];
    const float* b2   = (const float*)d_in[6];
    const float* W3   = (const float*)d_in[7];
    const float* b3   = (const float*)d_in[8];
    const float* Wc1  = (const float*)d_in[9];
    const float* bc1  = (const float*)d_in[10];
    const float* Wc2  = (const float*)d_in[11];
    const float* bc2  = (const float*)d_in[12];

    const int n = in_sizes[0] / 128;
    const int E = in_sizes[1] / 2;
    const int* src = ei;
    const int* dst = ei + E;

    __half* dA;
    float*  dB;
    cudaGetSymbolAddress((void**)&dA, g_A16);
    cudaGetSymbolAddress((void**)&dB, g_B);

    const int TB = 256;
    int gn   = (n + TB - 1) / TB;
    int gE4  = (E + 4 * TB - 1) / (4 * TB);
    int gn16 = (int)(((long long)n * 16 + TB - 1) / TB);
    int gW   = (int)(((long long)n * 32 + TB - 1) / TB);
    int gRow = (n + 63) / 64;
    int nb   = (n + SCAN_BLK - 1) / SCAN_BLK;

    // ---- CSR build ----
    k_hist<<<gE4, TB>>>(dst, E);                      // launch 1
    k_scan1<<<nb, 256>>>(n);                          // launch 2
    k_scan3<<<gn, TB>>>(n, E, nb);                    // launch 3
    k_sortscatter<<<gE4, TB>>>(src, dst, E);          // launch 4  <- profiled

    // layer 1
    k_gemm<128, false><<<gRow, TB>>>(x, W1, nullptr, dA, n);
    k_gather<<<gW, TB>>>(dA, dB, n);

    // layer 2
    k_gemm<64, true><<<gRow, TB>>>(dB, W2, b1, dA, n);
    k_gather<<<gW, TB>>>(dA, dB, n);

    // layer 3
    k_gemm<64, true><<<gRow, TB>>>(dB, W3, b2, dA, n);
    k_gather<<<gW, TB>>>(dA, dB, n);

    // mean-pool (fuses relu(B + b3)) + classifier
    k_pool<<<gn16, TB>>>(dB, b3, bat, n);
    k_classifier<<<NGRAPH, 32>>>(Wc1, bc1, Wc2, bc2, (float*)d_out);
}

// round 8
// speedup vs baseline: 1.1702x; 1.0016x over previous
#include <cuda_runtime.h>
#include <cuda_fp16.h>

#define N_HID 64
#define MAXN 100000
#define MAXE 3200000
#define NGRAPH 512
#define SCAN_BLK 1024
#define MAXPART 128

// Scratch (device globals — no allocation allowed; zero-initialized at load)
__device__ __align__(16) float  g_dinv[MAXN];
__device__ __align__(16) int    g_cnt2[MAXN];        // zero at entry (scan1 re-zeroes)
__device__ __align__(16) int    g_off[MAXN + 1];
__device__ __align__(16) int    g_cur[MAXN];         // write cursor (starts at g_off[i])
__device__ __align__(16) int    g_part[MAXPART];
__device__ __align__(16) int    g_esrc[MAXE + 8];    // sorted src indices (4B/edge)
__device__ __align__(16) __half g_A16[(size_t)MAXN * N_HID];  // A' = dinv[row] * h[row], fp16
__device__ __align__(16) float  g_B[(size_t)MAXN * N_HID];    // aggregated fp32
__device__ __align__(16) float  g_pool[NGRAPH * N_HID];
__device__ float g_cnt[NGRAPH];

// ---------------- histogram of dst (int4 loads) ----------------
__global__ void k_hist(const int* __restrict__ dst, int E) {
    int e4 = (blockIdx.x * blockDim.x + threadIdx.x) * 4;
    if (e4 + 3 < E) {
        int4 d = *(const int4*)(dst + e4);
        atomicAdd(&g_cnt2[d.x], 1);
        atomicAdd(&g_cnt2[d.y], 1);
        atomicAdd(&g_cnt2[d.z], 1);
        atomicAdd(&g_cnt2[d.w], 1);
    } else {
        for (int e = e4; e < E; e++) atomicAdd(&g_cnt2[dst[e]], 1);
    }
}

// ---------------- block scan (reads AND re-zeroes g_cnt2; derives dinv) ----------------
__global__ void __launch_bounds__(256) k_scan1(int n) {
    __shared__ int wt[8];
    __shared__ int wtex[8];
    const int t = threadIdx.x, lane = t & 31, warp = t >> 5;
    const int base = blockIdx.x * SCAN_BLK + t * 4;
    int a0 = (base + 0 < n) ? g_cnt2[base + 0] : 0;
    int a1 = (base + 1 < n) ? g_cnt2[base + 1] : 0;
    int a2 = (base + 2 < n) ? g_cnt2[base + 2] : 0;
    int a3 = (base + 3 < n) ? g_cnt2[base + 3] : 0;
    int sum4 = a0 + a1 + a2 + a3;
    int v = sum4;
#pragma unroll
    for (int o = 1; o < 32; o <<= 1) {
        int u = __shfl_up_sync(0xFFFFFFFFu, v, o);
        if (lane >= o) v += u;
    }
    if (lane == 31) wt[warp] = v;
    __syncthreads();
    if (t == 0) {
        int run = 0;
#pragma unroll
        for (int w = 0; w < 8; w++) { wtex[w] = run; run += wt[w]; }
        g_part[blockIdx.x] = run;
    }
    __syncthreads();
    int ex = v - sum4 + wtex[warp];
    if (base + 0 < n) { g_off[base + 0] = ex;                g_dinv[base + 0] = rsqrtf((float)a0 + 1.0f); g_cnt2[base + 0] = 0; }
    if (base + 1 < n) { g_off[base + 1] = ex + a0;           g_dinv[base + 1] = rsqrtf((float)a1 + 1.0f); g_cnt2[base + 1] = 0; }
    if (base + 2 < n) { g_off[base + 2] = ex + a0 + a1;      g_dinv[base + 2] = rsqrtf((float)a2 + 1.0f); g_cnt2[base + 2] = 0; }
    if (base + 3 < n) { g_off[base + 3] = ex + a0 + a1 + a2; g_dinv[base + 3] = rsqrtf((float)a3 + 1.0f); g_cnt2[base + 3] = 0; }
}

// ---------------- scan finalize: add block prefix; g_cur = g_off; zero pool ----------------
__global__ void __launch_bounds__(256) k_scan3(int n, int E, int nb) {
    __shared__ int sp[MAXPART];
    int t = threadIdx.x;
    if (t < MAXPART) sp[t] = (t < nb) ? g_part[t] : 0;
    __syncthreads();
    if (t == 0) {
        int run = 0;
        for (int i = 0; i < nb; i++) { int c = sp[i]; sp[i] = run; run += c; }
    }
    __syncthreads();
    int i = blockIdx.x * blockDim.x + t;
    if (i < n) {
        int o = g_off[i] + sp[i >> 10];
        g_off[i] = o;
        g_cur[i] = o;
    }
    if (i == 0) g_off[n] = E;
    if (i < NGRAPH * N_HID) g_pool[i] = 0.0f;
    if (i < NGRAPH) g_cnt[i] = 0.0f;
}

// ---------------- counting-sort by dst: store ONLY src ----------------
__global__ void k_sortscatter(const int* __restrict__ src, const int* __restrict__ dst, int E) {
    int e4 = (blockIdx.x * blockDim.x + threadIdx.x) * 4;
    if (e4 + 3 < E) {
        int4 s = *(const int4*)(src + e4);
        int4 d = *(const int4*)(dst + e4);
        { int r = atomicAdd(&g_cur[d.x], 1); g_esrc[r] = s.x; }
        { int r = atomicAdd(&g_cur[d.y], 1); g_esrc[r] = s.y; }
        { int r = atomicAdd(&g_cur[d.z], 1); g_esrc[r] = s.z; }
        { int r = atomicAdd(&g_cur[d.w], 1); g_esrc[r] = s.w; }
    } else {
        for (int e = e4; e < E; e++) {
            int r = atomicAdd(&g_cur[dst[e]], 1);
            g_esrc[r] = src[e];
        }
    }
}

// ---------------- packed f32x2 helpers ----------------
__device__ __forceinline__ unsigned long long pack2(float lo, float hi) {
    unsigned long long r;
    asm("mov.b64 %0, {%1, %2};" : "=l"(r) : "f"(lo), "f"(hi));
    return r;
}
__device__ __forceinline__ void fma2(unsigned long long& d, unsigned long long a, unsigned long long b) {
    asm("fma.rn.f32x2 %0, %1, %2, %0;" : "+l"(d) : "l"(a), "l"(b));
}
__device__ __forceinline__ float2 unpack2(unsigned long long v) {
    float lo, hi;
    asm("mov.b64 {%0, %1}, %2;" : "=f"(lo), "=f"(hi) : "l"(v));
    return make_float2(lo, hi);
}

// ---------------- GEMM (f32x2): A16[n][64] = dinv[row]*(act(X)@W), fp16 out ----------------
template <int K, bool PRE>
__global__ void __launch_bounds__(256) k_gemm(const float* __restrict__ X,
                                              const float* __restrict__ W,
                                              const float* __restrict__ pb,
                                              __half* __restrict__ H, int n) {
    __shared__ float Ws[64][64];
    __shared__ float Xs[64][65];   // pad to avoid bank conflicts on row-broadcast reads
    const int row0 = blockIdx.x * 64;
    const int tx = threadIdx.x & 15;
    const int ty = threadIdx.x >> 4;
    unsigned long long acc[4][2] = {};  // 4 rows x 4 cols (2x f32x2)

    for (int k0 = 0; k0 < K; k0 += 64) {
        for (int i = threadIdx.x; i < 64 * 64; i += 256) {
            int k = i >> 6, c = i & 63;
            Ws[k][c] = W[(size_t)(k0 + k) * 64 + c];
        }
        for (int i = threadIdx.x; i < 64 * 64; i += 256) {
            int r = i >> 6, k = i & 63;
            int row = row0 + r;
            float v = 0.0f;
            if (row < n) {
                v = X[(size_t)row * K + k0 + k];
                if (PRE) v = fmaxf(v + pb[k0 + k], 0.0f);
            }
            Xs[r][k] = v;
        }
        __syncthreads();
#pragma unroll
        for (int k = 0; k < 64; k++) {
            float4 wv = *(const float4*)&Ws[k][tx * 4];
            unsigned long long wlo = pack2(wv.x, wv.y);
            unsigned long long whi = pack2(wv.z, wv.w);
#pragma unroll
            for (int i = 0; i < 4; i++) {
                float x = Xs[ty * 4 + i][k];
                unsigned long long x2 = pack2(x, x);
                fma2(acc[i][0], x2, wlo);
                fma2(acc[i][1], x2, whi);
            }
        }
        __syncthreads();
    }
#pragma unroll
    for (int i = 0; i < 4; i++) {
        int row = row0 + ty * 4 + i;
        if (row < n) {
            float dv = g_dinv[row];
            float2 lo = unpack2(acc[i][0]);
            float2 hi = unpack2(acc[i][1]);
            union { uint2 u; __half2 h[2]; } pk;
            pk.h[0] = __floats2half2_rn(lo.x * dv, lo.y * dv);
            pk.h[1] = __floats2half2_rn(hi.x * dv, hi.y * dv);
            *(uint2*)&H[(size_t)row * 64 + tx * 4] = pk.u;
        }
    }
}

// ---------------- gather: warp/node, lane = half2 column, no weights ----------------
// out[d] = dinv[d] * ( sum_j A'[src_j] + A'[d] )
__global__ void __launch_bounds__(256) k_gather(const __half* __restrict__ Ain,
                                                float* __restrict__ Hout, int n) {
    int wid = (blockIdx.x * blockDim.x + threadIdx.x) >> 5;
    if (wid >= n) return;
    const int lane = threadIdx.x & 31;
    const int beg = g_off[wid];
    const int end = g_off[wid + 1];
    const __half2* A = (const __half2*)Ain;

    // self term
    float2 acc = __half22float2(A[(size_t)wid * 32 + lane]);

    int j = beg;
    while ((j & 3) && j < end) {
        float2 v = __half22float2(A[(size_t)g_esrc[j] * 32 + lane]);
        acc.x += v.x; acc.y += v.y;
        j++;
    }
    for (; j + 8 <= end; j += 8) {
        int4 q0 = *(const int4*)&g_esrc[j + 0];
        int4 q1 = *(const int4*)&g_esrc[j + 4];
        float2 v0 = __half22float2(A[(size_t)q0.x * 32 + lane]);
        float2 v1 = __half22float2(A[(size_t)q0.y * 32 + lane]);
        float2 v2 = __half22float2(A[(size_t)q0.z * 32 + lane]);
        float2 v3 = __half22float2(A[(size_t)q0.w * 32 + lane]);
        float2 v4 = __half22float2(A[(size_t)q1.x * 32 + lane]);
        float2 v5 = __half22float2(A[(size_t)q1.y * 32 + lane]);
        float2 v6 = __half22float2(A[(size_t)q1.z * 32 + lane]);
        float2 v7 = __half22float2(A[(size_t)q1.w * 32 + lane]);
        acc.x += v0.x; acc.y += v0.y;
        acc.x += v1.x; acc.y += v1.y;
        acc.x += v2.x; acc.y += v2.y;
        acc.x += v3.x; acc.y += v3.y;
        acc.x += v4.x; acc.y += v4.y;
        acc.x += v5.x; acc.y += v5.y;
        acc.x += v6.x; acc.y += v6.y;
        acc.x += v7.x; acc.y += v7.y;
    }
    for (; j + 4 <= end; j += 4) {
        int4 q = *(const int4*)&g_esrc[j];
        float2 v0 = __half22float2(A[(size_t)q.x * 32 + lane]);
        float2 v1 = __half22float2(A[(size_t)q.y * 32 + lane]);
        float2 v2 = __half22float2(A[(size_t)q.z * 32 + lane]);
        float2 v3 = __half22float2(A[(size_t)q.w * 32 + lane]);
        acc.x += v0.x; acc.y += v0.y;
        acc.x += v1.x; acc.y += v1.y;
        acc.x += v2.x; acc.y += v2.y;
        acc.x += v3.x; acc.y += v3.y;
    }
    for (; j < end; j++) {
        float2 v = __half22float2(A[(size_t)g_esrc[j] * 32 + lane]);
        acc.x += v.x; acc.y += v.y;
    }

    float dv = g_dinv[wid];
    float2 o = make_float2(acc.x * dv, acc.y * dv);
    *(float2*)(Hout + (size_t)wid * 64 + lane * 2) = o;
}

// ---------------- pooling ----------------
__device__ __forceinline__ void red_add_v4(float* p, float a, float b, float c, float d) {
    unsigned long long gp;
    asm("cvta.to.global.u64 %0, %1;" : "=l"(gp) : "l"(p));
    asm volatile("red.global.add.v4.f32 [%0], {%1, %2, %3, %4};"
                 :: "l"(gp), "f"(a), "f"(b), "f"(c), "f"(d) : "memory");
}

__global__ void k_pool(const float* __restrict__ H, const float* __restrict__ b3,
                       const int* __restrict__ batch, int n) {
    int idx = blockIdx.x * blockDim.x + threadIdx.x;
    int i = idx >> 4, c = idx & 15;
    if (i >= n) return;
    int g = batch[i];
    float4 h = *(const float4*)&H[(size_t)i * 64 + c * 4];
    float4 bb = *(const float4*)&b3[c * 4];
    h.x = fmaxf(h.x + bb.x, 0.0f);
    h.y = fmaxf(h.y + bb.y, 0.0f);
    h.z = fmaxf(h.z + bb.z, 0.0f);
    h.w = fmaxf(h.w + bb.w, 0.0f);
    red_add_v4(&g_pool[g * 64 + c * 4], h.x, h.y, h.z, h.w);
    if (c == 0) atomicAdd(&g_cnt[g], 1.0f);
}

// ---------------- classifier head ----------------
__global__ void k_classifier(const float* __restrict__ Wc1, const float* __restrict__ bc1,
                             const float* __restrict__ Wc2, const float* __restrict__ bc2,
                             float* __restrict__ out) {
    __shared__ float p[64];
    __shared__ float z[32];
    int g = blockIdx.x;
    int t = threadIdx.x;  // 32 threads
    float inv = 1.0f / fmaxf(g_cnt[g], 1.0f);
    p[t] = g_pool[g * 64 + t] * inv;
    p[t + 32] = g_pool[g * 64 + 32 + t] * inv;
    __syncwarp();
    float acc = bc1[t];
#pragma unroll
    for (int k = 0; k < 64; k++) acc += p[k] * Wc1[k * 32 + t];
    z[t] = fmaxf(acc, 0.0f);
    __syncwarp();
    if (t < 10) {
        float a = bc2[t];
#pragma unroll
        for (int k = 0; k < 32; k++) a += z[k] * Wc2[k * 10 + t];
        out[g * 10 + t] = a;
    }
}

extern "C" void kernel_launch(void* const* d_in, const int* in_sizes, int n_in,
                              void* d_out, int out_size) {
    const float* x    = (const float*)d_in[0];
    const int*   ei   = (const int*)d_in[1];
    const int*   bat  = (const int*)d_in[2];
    const float* W1   = (const float*)d_in[3];
    const float* b1   = (const float*)d_in[4];
    const float* W2   = (const float*)d_in[5];
    const float* b2   = (const float*)d_in[6];
    const float* W3   = (const float*)d_in[7];
    const float* b3   = (const float*)d_in[8];
    const float* Wc1  = (const float*)d_in[9];
    const float* bc1  = (const float*)d_in[10];
    const float* Wc2  = (const float*)d_in[11];
    const float* bc2  = (const float*)d_in[12];

    const int n = in_sizes[0] / 128;
    const int E = in_sizes[1] / 2;
    const int* src = ei;
    const int* dst = ei + E;

    __half* dA;
    float*  dB;
    cudaGetSymbolAddress((void**)&dA, g_A16);
    cudaGetSymbolAddress((void**)&dB, g_B);

    const int TB = 256;
    int gn   = (n + TB - 1) / TB;
    int gE4  = (E + 4 * TB - 1) / (4 * TB);
    int gn16 = (int)(((long long)n * 16 + TB - 1) / TB);
    int gW   = (int)(((long long)n * 32 + TB - 1) / TB);
    int gRow = (n + 63) / 64;
    int nb   = (n + SCAN_BLK - 1) / SCAN_BLK;

    // ---- CSR build + layer-1 GEMM (gemm1 independent of sortscatter -> profiled slot 4) ----
    k_hist<<<gE4, TB>>>(dst, E);                      // launch 1
    k_scan1<<<nb, 256>>>(n);                          // launch 2
    k_scan3<<<gn, TB>>>(n, E, nb);                    // launch 3
    k_gemm<128, false><<<gRow, TB>>>(x, W1, nullptr, dA, n);  // launch 4 <- profiled
    k_sortscatter<<<gE4, TB>>>(src, dst, E);          // launch 5

    // layer 1 aggregate
    k_gather<<<gW, TB>>>(dA, dB, n);

    // layer 2
    k_gemm<64, true><<<gRow, TB>>>(dB, W2, b1, dA, n);
    k_gather<<<gW, TB>>>(dA, dB, n);

    // layer 3
    k_gemm<64, true><<<gRow, TB>>>(dB, W3, b2, dA, n);
    k_gather<<<gW, TB>>>(dA, dB, n);

    // mean-pool (fuses relu(B + b3)) + classifier
    k_pool<<<gn16, TB>>>(dB, b3, bat, n);
    k_classifier<<<NGRAPH, 32>>>(Wc1, bc1, Wc2, bc2, (float*)d_out);
}

// round 9
// speedup vs baseline: 1.3002x; 1.1111x over previous
#include <cuda_runtime.h>
#include <cuda_fp16.h>

#define N_HID 64
#define MAXN 100000
#define MAXE 3200000
#define NGRAPH 512
#define SCAN_BLK 1024
#define MAXPART 128

// Scratch (device globals — no allocation allowed; zero-initialized at load)
__device__ __align__(16) float  g_dinv[MAXN];
__device__ __align__(16) int    g_cnt2[MAXN];        // zero at entry (scan1 re-zeroes)
__device__ __align__(16) int    g_off[MAXN + 1];
__device__ __align__(16) int    g_cur[MAXN];         // write cursor (starts at g_off[i])
__device__ __align__(16) int    g_part[MAXPART];
__device__ __align__(16) int    g_esrc[MAXE + 8];    // sorted src indices (4B/edge)
__device__ __align__(16) __half g_A16[(size_t)MAXN * N_HID];  // A' = dinv[row] * h[row], fp16
__device__ __align__(16) float  g_B[(size_t)MAXN * N_HID];    // aggregated fp32
__device__ __align__(16) float  g_pool[NGRAPH * N_HID];
__device__ float g_cnt[NGRAPH];

// ---------------- histogram of dst (int4 loads) ----------------
__global__ void k_hist(const int* __restrict__ dst, int E) {
    int e4 = (blockIdx.x * blockDim.x + threadIdx.x) * 4;
    if (e4 + 3 < E) {
        int4 d = *(const int4*)(dst + e4);
        atomicAdd(&g_cnt2[d.x], 1);
        atomicAdd(&g_cnt2[d.y], 1);
        atomicAdd(&g_cnt2[d.z], 1);
        atomicAdd(&g_cnt2[d.w], 1);
    } else {
        for (int e = e4; e < E; e++) atomicAdd(&g_cnt2[dst[e]], 1);
    }
}

// ---------------- block scan (reads AND re-zeroes g_cnt2; derives dinv) ----------------
__global__ void __launch_bounds__(256) k_scan1(int n) {
    __shared__ int wt[8];
    __shared__ int wtex[8];
    const int t = threadIdx.x, lane = t & 31, warp = t >> 5;
    const int base = blockIdx.x * SCAN_BLK + t * 4;
    int a0 = (base + 0 < n) ? g_cnt2[base + 0] : 0;
    int a1 = (base + 1 < n) ? g_cnt2[base + 1] : 0;
    int a2 = (base + 2 < n) ? g_cnt2[base + 2] : 0;
    int a3 = (base + 3 < n) ? g_cnt2[base + 3] : 0;
    int sum4 = a0 + a1 + a2 + a3;
    int v = sum4;
#pragma unroll
    for (int o = 1; o < 32; o <<= 1) {
        int u = __shfl_up_sync(0xFFFFFFFFu, v, o);
        if (lane >= o) v += u;
    }
    if (lane == 31) wt[warp] = v;
    __syncthreads();
    if (t == 0) {
        int run = 0;
#pragma unroll
        for (int w = 0; w < 8; w++) { wtex[w] = run; run += wt[w]; }
        g_part[blockIdx.x] = run;
    }
    __syncthreads();
    int ex = v - sum4 + wtex[warp];
    if (base + 0 < n) { g_off[base + 0] = ex;                g_dinv[base + 0] = rsqrtf((float)a0 + 1.0f); g_cnt2[base + 0] = 0; }
    if (base + 1 < n) { g_off[base + 1] = ex + a0;           g_dinv[base + 1] = rsqrtf((float)a1 + 1.0f); g_cnt2[base + 1] = 0; }
    if (base + 2 < n) { g_off[base + 2] = ex + a0 + a1;      g_dinv[base + 2] = rsqrtf((float)a2 + 1.0f); g_cnt2[base + 2] = 0; }
    if (base + 3 < n) { g_off[base + 3] = ex + a0 + a1 + a2; g_dinv[base + 3] = rsqrtf((float)a3 + 1.0f); g_cnt2[base + 3] = 0; }
}

// ---------------- scan finalize: add block prefix; g_cur = g_off; zero pool ----------------
__global__ void __launch_bounds__(256) k_scan3(int n, int E, int nb) {
    __shared__ int sp[MAXPART];
    int t = threadIdx.x;
    if (t < MAXPART) sp[t] = (t < nb) ? g_part[t] : 0;
    __syncthreads();
    if (t == 0) {
        int run = 0;
        for (int i = 0; i < nb; i++) { int c = sp[i]; sp[i] = run; run += c; }
    }
    __syncthreads();
    int i = blockIdx.x * blockDim.x + t;
    if (i < n) {
        int o = g_off[i] + sp[i >> 10];
        g_off[i] = o;
        g_cur[i] = o;
    }
    if (i == 0) g_off[n] = E;
    if (i < NGRAPH * N_HID) g_pool[i] = 0.0f;
    if (i < NGRAPH) g_cnt[i] = 0.0f;
}

// ---------------- counting-sort by dst: store ONLY src ----------------
__global__ void k_sortscatter(const int* __restrict__ src, const int* __restrict__ dst, int E) {
    int e4 = (blockIdx.x * blockDim.x + threadIdx.x) * 4;
    if (e4 + 3 < E) {
        int4 s = *(const int4*)(src + e4);
        int4 d = *(const int4*)(dst + e4);
        { int r = atomicAdd(&g_cur[d.x], 1); g_esrc[r] = s.x; }
        { int r = atomicAdd(&g_cur[d.y], 1); g_esrc[r] = s.y; }
        { int r = atomicAdd(&g_cur[d.z], 1); g_esrc[r] = s.z; }
        { int r = atomicAdd(&g_cur[d.w], 1); g_esrc[r] = s.w; }
    } else {
        for (int e = e4; e < E; e++) {
            int r = atomicAdd(&g_cur[dst[e]], 1);
            g_esrc[r] = src[e];
        }
    }
}

// ---------------- HMMA m16n8k16 wrapper ----------------
__device__ __forceinline__ void mma16816(float* c,
                                         unsigned a0, unsigned a1, unsigned a2, unsigned a3,
                                         unsigned b0, unsigned b1) {
    asm volatile(
        "mma.sync.aligned.m16n8k16.row.col.f32.f16.f16.f32 "
        "{%0,%1,%2,%3}, {%4,%5,%6,%7}, {%8,%9}, {%0,%1,%2,%3};"
        : "+f"(c[0]), "+f"(c[1]), "+f"(c[2]), "+f"(c[3])
        : "r"(a0), "r"(a1), "r"(a2), "r"(a3), "r"(b0), "r"(b1));
}

// ---------------- GEMM (tensor core): A16 = dinv[row]*(act(X)@W), fp16 out ----------------
// Block: 128 rows x 64 cols; 8 warps, warp w owns rows [w*16, w*16+16).
template <int K, bool PRE>
__global__ void __launch_bounds__(256) k_gemm(const float* __restrict__ X,
                                              const float* __restrict__ W,
                                              const float* __restrict__ pb,
                                              __half* __restrict__ H, int n) {
    __shared__ __half Xh[128][72];       // 64-k chunk, +8 pad -> conflict-free frags
    __shared__ __half Wt[64][K + 8];     // transposed W, fp16
    const int tid = threadIdx.x;
    const int wid = tid >> 5;
    const int lane = tid & 31;
    const int gID = lane >> 2;
    const int tig = lane & 3;
    const int row0 = blockIdx.x * 128;

    // Wt[c][k] = (half)W[k][c]
    for (int i = tid; i < K * 64; i += 256) {
        int k = i >> 6, c = i & 63;
        Wt[c][k] = __float2half(W[(size_t)k * 64 + c]);
    }

    float acc[8][4] = {};  // 8 n-tiles (n8) x 4 f32

    for (int k0 = 0; k0 < K; k0 += 64) {
        __syncthreads();   // Xh reuse across chunks (also orders Wt before first use)
        // Xh[r][k] = (half)act(X[row0+r][k0+k]); half2 writes, conflict-free
        for (int i = tid; i < 128 * 32; i += 256) {
            int r = i >> 5, kp = (i & 31) * 2;
            int row = row0 + r;
            float2 xv = make_float2(0.0f, 0.0f);
            if (row < n) {
                xv = *(const float2*)(X + (size_t)row * K + k0 + kp);
                if (PRE) {
                    xv.x = fmaxf(xv.x + pb[k0 + kp], 0.0f);
                    xv.y = fmaxf(xv.y + pb[k0 + kp + 1], 0.0f);
                }
            }
            *(__half2*)&Xh[r][kp] = __floats2half2_rn(xv.x, xv.y);
        }
        __syncthreads();

#pragma unroll
        for (int ks = 0; ks < 4; ks++) {
            const int kb = ks * 16;
            const int r0 = wid * 16 + gID;
            unsigned a0 = *(const unsigned*)&Xh[r0][kb + tig * 2];
            unsigned a1 = *(const unsigned*)&Xh[r0 + 8][kb + tig * 2];
            unsigned a2 = *(const unsigned*)&Xh[r0][kb + tig * 2 + 8];
            unsigned a3 = *(const unsigned*)&Xh[r0 + 8][kb + tig * 2 + 8];
#pragma unroll
            for (int nt = 0; nt < 8; nt++) {
                int c = nt * 8 + gID;
                unsigned b0 = *(const unsigned*)&Wt[c][k0 + kb + tig * 2];
                unsigned b1 = *(const unsigned*)&Wt[c][k0 + kb + tig * 2 + 8];
                mma16816(acc[nt], a0, a1, a2, a3, b0, b1);
            }
        }
    }

    // epilogue: scale by dinv[row], store fp16
    const int r0 = row0 + wid * 16 + gID;
    const int r1 = r0 + 8;
    float dv0 = (r0 < n) ? g_dinv[r0] : 0.0f;
    float dv1 = (r1 < n) ? g_dinv[r1] : 0.0f;
#pragma unroll
    for (int nt = 0; nt < 8; nt++) {
        int c = nt * 8 + tig * 2;
        if (r0 < n) {
            __half2 h = __floats2half2_rn(acc[nt][0] * dv0, acc[nt][1] * dv0);
            *(__half2*)&H[(size_t)r0 * 64 + c] = h;
        }
        if (r1 < n) {
            __half2 h = __floats2half2_rn(acc[nt][2] * dv1, acc[nt][3] * dv1);
            *(__half2*)&H[(size_t)r1 * 64 + c] = h;
        }
    }
}

// ---------------- gather: warp/node, lane = half2 column, no weights ----------------
// out[d] = dinv[d] * ( sum_j A'[src_j] + A'[d] )
__global__ void __launch_bounds__(256) k_gather(const __half* __restrict__ Ain,
                                                float* __restrict__ Hout, int n) {
    int wid = (blockIdx.x * blockDim.x + threadIdx.x) >> 5;
    if (wid >= n) return;
    const int lane = threadIdx.x & 31;
    const int beg = g_off[wid];
    const int end = g_off[wid + 1];
    const __half2* A = (const __half2*)Ain;

    float2 acc = __half22float2(A[(size_t)wid * 32 + lane]);  // self term

    int j = beg;
    while ((j & 3) && j < end) {
        float2 v = __half22float2(A[(size_t)g_esrc[j] * 32 + lane]);
        acc.x += v.x; acc.y += v.y;
        j++;
    }
    for (; j + 8 <= end; j += 8) {
        int4 q0 = *(const int4*)&g_esrc[j + 0];
        int4 q1 = *(const int4*)&g_esrc[j + 4];
        float2 v0 = __half22float2(A[(size_t)q0.x * 32 + lane]);
        float2 v1 = __half22float2(A[(size_t)q0.y * 32 + lane]);
        float2 v2 = __half22float2(A[(size_t)q0.z * 32 + lane]);
        float2 v3 = __half22float2(A[(size_t)q0.w * 32 + lane]);
        float2 v4 = __half22float2(A[(size_t)q1.x * 32 + lane]);
        float2 v5 = __half22float2(A[(size_t)q1.y * 32 + lane]);
        float2 v6 = __half22float2(A[(size_t)q1.z * 32 + lane]);
        float2 v7 = __half22float2(A[(size_t)q1.w * 32 + lane]);
        acc.x += v0.x; acc.y += v0.y;
        acc.x += v1.x; acc.y += v1.y;
        acc.x += v2.x; acc.y += v2.y;
        acc.x += v3.x; acc.y += v3.y;
        acc.x += v4.x; acc.y += v4.y;
        acc.x += v5.x; acc.y += v5.y;
        acc.x += v6.x; acc.y += v6.y;
        acc.x += v7.x; acc.y += v7.y;
    }
    for (; j + 4 <= end; j += 4) {
        int4 q = *(const int4*)&g_esrc[j];
        float2 v0 = __half22float2(A[(size_t)q.x * 32 + lane]);
        float2 v1 = __half22float2(A[(size_t)q.y * 32 + lane]);
        float2 v2 = __half22float2(A[(size_t)q.z * 32 + lane]);
        float2 v3 = __half22float2(A[(size_t)q.w * 32 + lane]);
        acc.x += v0.x; acc.y += v0.y;
        acc.x += v1.x; acc.y += v1.y;
        acc.x += v2.x; acc.y += v2.y;
        acc.x += v3.x; acc.y += v3.y;
    }
    for (; j < end; j++) {
        float2 v = __half22float2(A[(size_t)g_esrc[j] * 32 + lane]);
        acc.x += v.x; acc.y += v.y;
    }

    float dv = g_dinv[wid];
    float2 o = make_float2(acc.x * dv, acc.y * dv);
    *(float2*)(Hout + (size_t)wid * 64 + lane * 2) = o;
}

// ---------------- pooling ----------------
__device__ __forceinline__ void red_add_v4(float* p, float a, float b, float c, float d) {
    unsigned long long gp;
    asm("cvta.to.global.u64 %0, %1;" : "=l"(gp) : "l"(p));
    asm volatile("red.global.add.v4.f32 [%0], {%1, %2, %3, %4};"
                 :: "l"(gp), "f"(a), "f"(b), "f"(c), "f"(d) : "memory");
}

__global__ void k_pool(const float* __restrict__ H, const float* __restrict__ b3,
                       const int* __restrict__ batch, int n) {
    int idx = blockIdx.x * blockDim.x + threadIdx.x;
    int i = idx >> 4, c = idx & 15;
    if (i >= n) return;
    int g = batch[i];
    float4 h = *(const float4*)&H[(size_t)i * 64 + c * 4];
    float4 bb = *(const float4*)&b3[c * 4];
    h.x = fmaxf(h.x + bb.x, 0.0f);
    h.y = fmaxf(h.y + bb.y, 0.0f);
    h.z = fmaxf(h.z + bb.z, 0.0f);
    h.w = fmaxf(h.w + bb.w, 0.0f);
    red_add_v4(&g_pool[g * 64 + c * 4], h.x, h.y, h.z, h.w);
    if (c == 0) atomicAdd(&g_cnt[g], 1.0f);
}

// ---------------- classifier head ----------------
__global__ void k_classifier(const float* __restrict__ Wc1, const float* __restrict__ bc1,
                             const float* __restrict__ Wc2, const float* __restrict__ bc2,
                             float* __restrict__ out) {
    __shared__ float p[64];
    __shared__ float z[32];
    int g = blockIdx.x;
    int t = threadIdx.x;  // 32 threads
    float inv = 1.0f / fmaxf(g_cnt[g], 1.0f);
    p[t] = g_pool[g * 64 + t] * inv;
    p[t + 32] = g_pool[g * 64 + 32 + t] * inv;
    __syncwarp();
    float acc = bc1[t];
#pragma unroll
    for (int k = 0; k < 64; k++) acc += p[k] * Wc1[k * 32 + t];
    z[t] = fmaxf(acc, 0.0f);
    __syncwarp();
    if (t < 10) {
        float a = bc2[t];
#pragma unroll
        for (int k = 0; k < 32; k++) a += z[k] * Wc2[k * 10 + t];
        out[g * 10 + t] = a;
    }
}

extern "C" void kernel_launch(void* const* d_in, const int* in_sizes, int n_in,
                              void* d_out, int out_size) {
    const float* x    = (const float*)d_in[0];
    const int*   ei   = (const int*)d_in[1];
    const int*   bat  = (const int*)d_in[2];
    const float* W1   = (const float*)d_in[3];
    const float* b1   = (const float*)d_in[4];
    const float* W2   = (const float*)d_in[5];
    const float* b2   = (const float*)d_in[6];
    const float* W3   = (const float*)d_in[7];
    const float* b3   = (const float*)d_in[8];
    const float* Wc1  = (const float*)d_in[9];
    const float* bc1  = (const float*)d_in[10];
    const float* Wc2  = (const float*)d_in[11];
    const float* bc2  = (const float*)d_in[12];

    const int n = in_sizes[0] / 128;
    const int E = in_sizes[1] / 2;
    const int* src = ei;
    const int* dst = ei + E;

    __half* dA;
    float*  dB;
    cudaGetSymbolAddress((void**)&dA, g_A16);
    cudaGetSymbolAddress((void**)&dB, g_B);

    const int TB = 256;
    int gn    = (n + TB - 1) / TB;
    int gE4   = (E + 4 * TB - 1) / (4 * TB);
    int gn16  = (int)(((long long)n * 16 + TB - 1) / TB);
    int gW    = (int)(((long long)n * 32 + TB - 1) / TB);
    int gRow2 = (n + 127) / 128;
    int nb    = (n + SCAN_BLK - 1) / SCAN_BLK;

    // ---- CSR build + layer-1 GEMM (slot 4 profiled) ----
    k_hist<<<gE4, TB>>>(dst, E);                      // launch 1
    k_scan1<<<nb, 256>>>(n);                          // launch 2
    k_scan3<<<gn, TB>>>(n, E, nb);                    // launch 3
    k_gemm<128, false><<<gRow2, TB>>>(x, W1, nullptr, dA, n);  // launch 4 <- profiled
    k_sortscatter<<<gE4, TB>>>(src, dst, E);          // launch 5

    // layer 1 aggregate
    k_gather<<<gW, TB>>>(dA, dB, n);

    // layer 2
    k_gemm<64, true><<<gRow2, TB>>>(dB, W2, b1, dA, n);
    k_gather<<<gW, TB>>>(dA, dB, n);

    // layer 3
    k_gemm<64, true><<<gRow2, TB>>>(dB, W3, b2, dA, n);
    k_gather<<<gW, TB>>>(dA, dB, n);

    // mean-pool (fuses relu(B + b3)) + classifier
    k_pool<<<gn16, TB>>>(dB, b3, bat, n);
    k_classifier<<<NGRAPH, 32>>>(Wc1, bc1, Wc2, bc2, (float*)d_out);
}

// round 10
// speedup vs baseline: 1.3641x; 1.0492x over previous
#include <cuda_runtime.h>
#include <cuda_fp16.h>

#define N_HID 64
#define MAXN 100000
#define MAXE 3200000
#define NGRAPH 512
#define SCAN_BLK 1024
#define MAXPART 128

// Scratch (device globals — no allocation allowed; zero-initialized at load)
__device__ __align__(16) float  g_dinv[MAXN];
__device__ __align__(16) int    g_cnt2[MAXN];        // zero at entry (scan1 re-zeroes)
__device__ __align__(16) int    g_off[MAXN + 1];
__device__ __align__(16) int    g_cur[MAXN];         // write cursor (starts at g_off[i])
__device__ __align__(16) int    g_part[MAXPART];
__device__ __align__(16) int    g_esrc[MAXE + 8];    // sorted src indices (4B/edge)
__device__ __align__(16) __half g_A16[(size_t)MAXN * N_HID];  // A' = dinv[row]*h[row], fp16
__device__ __align__(16) float  g_B[(size_t)MAXN * N_HID];    // aggregated fp32
__device__ __align__(16) float  g_pool[NGRAPH * N_HID];
__device__ float g_cnt[NGRAPH];

// ---------------- histogram of dst (int4 loads) ----------------
__global__ void k_hist(const int* __restrict__ dst, int E) {
    int e4 = (blockIdx.x * blockDim.x + threadIdx.x) * 4;
    if (e4 + 3 < E) {
        int4 d = *(const int4*)(dst + e4);
        atomicAdd(&g_cnt2[d.x], 1);
        atomicAdd(&g_cnt2[d.y], 1);
        atomicAdd(&g_cnt2[d.z], 1);
        atomicAdd(&g_cnt2[d.w], 1);
    } else {
        for (int e = e4; e < E; e++) atomicAdd(&g_cnt2[dst[e]], 1);
    }
}

// ---------------- block scan (reads AND re-zeroes g_cnt2; derives dinv) ----------------
__global__ void __launch_bounds__(256) k_scan1(int n) {
    __shared__ int wt[8];
    __shared__ int wtex[8];
    const int t = threadIdx.x, lane = t & 31, warp = t >> 5;
    const int base = blockIdx.x * SCAN_BLK + t * 4;
    int a0 = (base + 0 < n) ? g_cnt2[base + 0] : 0;
    int a1 = (base + 1 < n) ? g_cnt2[base + 1] : 0;
    int a2 = (base + 2 < n) ? g_cnt2[base + 2] : 0;
    int a3 = (base + 3 < n) ? g_cnt2[base + 3] : 0;
    int sum4 = a0 + a1 + a2 + a3;
    int v = sum4;
#pragma unroll
    for (int o = 1; o < 32; o <<= 1) {
        int u = __shfl_up_sync(0xFFFFFFFFu, v, o);
        if (lane >= o) v += u;
    }
    if (lane == 31) wt[warp] = v;
    __syncthreads();
    if (t == 0) {
        int run = 0;
#pragma unroll
        for (int w = 0; w < 8; w++) { wtex[w] = run; run += wt[w]; }
        g_part[blockIdx.x] = run;
    }
    __syncthreads();
    int ex = v - sum4 + wtex[warp];
    if (base + 0 < n) { g_off[base + 0] = ex;                g_dinv[base + 0] = rsqrtf((float)a0 + 1.0f); g_cnt2[base + 0] = 0; }
    if (base + 1 < n) { g_off[base + 1] = ex + a0;           g_dinv[base + 1] = rsqrtf((float)a1 + 1.0f); g_cnt2[base + 1] = 0; }
    if (base + 2 < n) { g_off[base + 2] = ex + a0 + a1;      g_dinv[base + 2] = rsqrtf((float)a2 + 1.0f); g_cnt2[base + 2] = 0; }
    if (base + 3 < n) { g_off[base + 3] = ex + a0 + a1 + a2; g_dinv[base + 3] = rsqrtf((float)a3 + 1.0f); g_cnt2[base + 3] = 0; }
}

// ---------------- scan finalize: add block prefix; g_cur = g_off; zero pool ----------------
__global__ void __launch_bounds__(256) k_scan3(int n, int E, int nb) {
    __shared__ int sp[MAXPART];
    int t = threadIdx.x;
    if (t < MAXPART) sp[t] = (t < nb) ? g_part[t] : 0;
    __syncthreads();
    if (t == 0) {
        int run = 0;
        for (int i = 0; i < nb; i++) { int c = sp[i]; sp[i] = run; run += c; }
    }
    __syncthreads();
    int i = blockIdx.x * blockDim.x + t;
    if (i < n) {
        int o = g_off[i] + sp[i >> 10];
        g_off[i] = o;
        g_cur[i] = o;
    }
    if (i == 0) g_off[n] = E;
    if (i < NGRAPH * N_HID) g_pool[i] = 0.0f;
    if (i < NGRAPH) g_cnt[i] = 0.0f;
}

// ---------------- counting-sort by dst: store ONLY src ----------------
__global__ void k_sortscatter(const int* __restrict__ src, const int* __restrict__ dst, int E) {
    int e4 = (blockIdx.x * blockDim.x + threadIdx.x) * 4;
    if (e4 + 3 < E) {
        int4 s = *(const int4*)(src + e4);
        int4 d = *(const int4*)(dst + e4);
        { int r = atomicAdd(&g_cur[d.x], 1); g_esrc[r] = s.x; }
        { int r = atomicAdd(&g_cur[d.y], 1); g_esrc[r] = s.y; }
        { int r = atomicAdd(&g_cur[d.z], 1); g_esrc[r] = s.z; }
        { int r = atomicAdd(&g_cur[d.w], 1); g_esrc[r] = s.w; }
    } else {
        for (int e = e4; e < E; e++) {
            int r = atomicAdd(&g_cur[dst[e]], 1);
            g_esrc[r] = src[e];
        }
    }
}

// ---------------- HMMA m16n8k16 wrapper ----------------
__device__ __forceinline__ void mma16816(float* c,
                                         unsigned a0, unsigned a1, unsigned a2, unsigned a3,
                                         unsigned b0, unsigned b1) {
    asm volatile(
        "mma.sync.aligned.m16n8k16.row.col.f32.f16.f16.f32 "
        "{%0,%1,%2,%3}, {%4,%5,%6,%7}, {%8,%9}, {%0,%1,%2,%3};"
        : "+f"(c[0]), "+f"(c[1]), "+f"(c[2]), "+f"(c[3])
        : "r"(a0), "r"(a1), "r"(a2), "r"(a3), "r"(b0), "r"(b1));
}

// ---------------- split helpers (fp32 -> hi/lo fp16 pair) ----------------
__device__ __forceinline__ void split2(float x, float y, __half2& hi, __half2& lo) {
    hi = __floats2half2_rn(x, y);
    float2 h = __half22float2(hi);
    lo = __floats2half2_rn(x - h.x, y - h.y);
}

// ---------------- GEMM (split-fp16 tensor core): A16 = dinv[row]*(act(X)@W) ----------------
// Block: 128 rows x 64 cols; 8 warps x m16; k-chunk 32; 3-product split MMA (~fp32 accuracy).
template <int K, bool PRE>
__global__ void __launch_bounds__(256) k_gemm(const float* __restrict__ X,
                                              const float* __restrict__ W,
                                              const float* __restrict__ pb,
                                              __half* __restrict__ H, int n) {
    __shared__ __half Xh[128][40], Xl[128][40];   // 32-k chunk, +8 pad
    __shared__ __half Wh[64][40],  Wl[64][40];    // transposed W chunk
    const int tid = threadIdx.x;
    const int wid = tid >> 5;
    const int lane = tid & 31;
    const int gID = lane >> 2;
    const int tig = lane & 3;
    const int row0 = blockIdx.x * 128;

    float acc[8][4] = {};  // 8 n-tiles x 4 f32

    for (int k0 = 0; k0 < K; k0 += 32) {
        __syncthreads();
        // W chunk: Wt[c][k] split hi/lo
        for (int i = tid; i < 32 * 64; i += 256) {
            int k = i >> 6, c = i & 63;
            float w = W[(size_t)(k0 + k) * 64 + c];
            __half hh = __float2half_rn(w);
            Wh[c][k] = hh;
            Wl[c][k] = __float2half_rn(w - __half2float(hh));
        }
        // X chunk: float4 loads, split hi/lo
        for (int i = tid; i < 128 * 8; i += 256) {
            int r = i >> 3, q = (i & 7) * 4;
            int row = row0 + r;
            float4 xv = make_float4(0.f, 0.f, 0.f, 0.f);
            if (row < n) {
                xv = *(const float4*)(X + (size_t)row * K + k0 + q);
                if (PRE) {
                    xv.x = fmaxf(xv.x + pb[k0 + q + 0], 0.f);
                    xv.y = fmaxf(xv.y + pb[k0 + q + 1], 0.f);
                    xv.z = fmaxf(xv.z + pb[k0 + q + 2], 0.f);
                    xv.w = fmaxf(xv.w + pb[k0 + q + 3], 0.f);
                }
            }
            __half2 h0, l0, h1, l1;
            split2(xv.x, xv.y, h0, l0);
            split2(xv.z, xv.w, h1, l1);
            *(__half2*)&Xh[r][q]     = h0;
            *(__half2*)&Xh[r][q + 2] = h1;
            *(__half2*)&Xl[r][q]     = l0;
            *(__half2*)&Xl[r][q + 2] = l1;
        }
        __syncthreads();

#pragma unroll
        for (int ks = 0; ks < 2; ks++) {
            const int kb = ks * 16;
            const int r0 = wid * 16 + gID;
            unsigned ah0 = *(const unsigned*)&Xh[r0][kb + tig * 2];
            unsigned ah1 = *(const unsigned*)&Xh[r0 + 8][kb + tig * 2];
            unsigned ah2 = *(const unsigned*)&Xh[r0][kb + tig * 2 + 8];
            unsigned ah3 = *(const unsigned*)&Xh[r0 + 8][kb + tig * 2 + 8];
            unsigned al0 = *(const unsigned*)&Xl[r0][kb + tig * 2];
            unsigned al1 = *(const unsigned*)&Xl[r0 + 8][kb + tig * 2];
            unsigned al2 = *(const unsigned*)&Xl[r0][kb + tig * 2 + 8];
            unsigned al3 = *(const unsigned*)&Xl[r0 + 8][kb + tig * 2 + 8];
#pragma unroll
            for (int nt = 0; nt < 8; nt++) {
                int c = nt * 8 + gID;
                unsigned bh0 = *(const unsigned*)&Wh[c][kb + tig * 2];
                unsigned bh1 = *(const unsigned*)&Wh[c][kb + tig * 2 + 8];
                unsigned bl0 = *(const unsigned*)&Wl[c][kb + tig * 2];
                unsigned bl1 = *(const unsigned*)&Wl[c][kb + tig * 2 + 8];
                mma16816(acc[nt], ah0, ah1, ah2, ah3, bh0, bh1);  // Xh*Wh
                mma16816(acc[nt], ah0, ah1, ah2, ah3, bl0, bl1);  // Xh*Wl
                mma16816(acc[nt], al0, al1, al2, al3, bh0, bh1);  // Xl*Wh
            }
        }
    }

    // epilogue: scale by dinv[row], store fp16
    const int r0 = row0 + wid * 16 + gID;
    const int r1 = r0 + 8;
    float dv0 = (r0 < n) ? g_dinv[r0] : 0.0f;
    float dv1 = (r1 < n) ? g_dinv[r1] : 0.0f;
#pragma unroll
    for (int nt = 0; nt < 8; nt++) {
        int c = nt * 8 + tig * 2;
        if (r0 < n) {
            __half2 h = __floats2half2_rn(acc[nt][0] * dv0, acc[nt][1] * dv0);
            *(__half2*)&H[(size_t)r0 * 64 + c] = h;
        }
        if (r1 < n) {
            __half2 h = __floats2half2_rn(acc[nt][2] * dv1, acc[nt][3] * dv1);
            *(__half2*)&H[(size_t)r1 * 64 + c] = h;
        }
    }
}

// ---------------- gather core ----------------
__device__ __forceinline__ float2 gather_row(const __half2* A, int wid, int lane) {
    const int beg = g_off[wid];
    const int end = g_off[wid + 1];
    float2 acc = __half22float2(A[(size_t)wid * 32 + lane]);  // self term
    int j = beg;
    while ((j & 3) && j < end) {
        float2 v = __half22float2(A[(size_t)g_esrc[j] * 32 + lane]);
        acc.x += v.x; acc.y += v.y;
        j++;
    }
    for (; j + 8 <= end; j += 8) {
        int4 q0 = *(const int4*)&g_esrc[j + 0];
        int4 q1 = *(const int4*)&g_esrc[j + 4];
        float2 v0 = __half22float2(A[(size_t)q0.x * 32 + lane]);
        float2 v1 = __half22float2(A[(size_t)q0.y * 32 + lane]);
        float2 v2 = __half22float2(A[(size_t)q0.z * 32 + lane]);
        float2 v3 = __half22float2(A[(size_t)q0.w * 32 + lane]);
        float2 v4 = __half22float2(A[(size_t)q1.x * 32 + lane]);
        float2 v5 = __half22float2(A[(size_t)q1.y * 32 + lane]);
        float2 v6 = __half22float2(A[(size_t)q1.z * 32 + lane]);
        float2 v7 = __half22float2(A[(size_t)q1.w * 32 + lane]);
        acc.x += v0.x; acc.y += v0.y;
        acc.x += v1.x; acc.y += v1.y;
        acc.x += v2.x; acc.y += v2.y;
        acc.x += v3.x; acc.y += v3.y;
        acc.x += v4.x; acc.y += v4.y;
        acc.x += v5.x; acc.y += v5.y;
        acc.x += v6.x; acc.y += v6.y;
        acc.x += v7.x; acc.y += v7.y;
    }
    for (; j + 4 <= end; j += 4) {
        int4 q = *(const int4*)&g_esrc[j];
        float2 v0 = __half22float2(A[(size_t)q.x * 32 + lane]);
        float2 v1 = __half22float2(A[(size_t)q.y * 32 + lane]);
        float2 v2 = __half22float2(A[(size_t)q.z * 32 + lane]);
        float2 v3 = __half22float2(A[(size_t)q.w * 32 + lane]);
        acc.x += v0.x; acc.y += v0.y;
        acc.x += v1.x; acc.y += v1.y;
        acc.x += v2.x; acc.y += v2.y;
        acc.x += v3.x; acc.y += v3.y;
    }
    for (; j < end; j++) {
        float2 v = __half22float2(A[(size_t)g_esrc[j] * 32 + lane]);
        acc.x += v.x; acc.y += v.y;
    }
    return acc;
}

// gather -> fp32 rows (layers 1,2)
__global__ void __launch_bounds__(256) k_gather(const __half* __restrict__ Ain,
                                                float* __restrict__ Hout, int n) {
    int wid = (blockIdx.x * blockDim.x + threadIdx.x) >> 5;
    if (wid >= n) return;
    const int lane = threadIdx.x & 31;
    float2 acc = gather_row((const __half2*)Ain, wid, lane);
    float dv = g_dinv[wid];
    float2 o = make_float2(acc.x * dv, acc.y * dv);
    *(float2*)(Hout + (size_t)wid * 64 + lane * 2) = o;
}

// gather fused with mean-pool accumulation (layer 3): no B write, no pool pass
__device__ __forceinline__ void red_add_v2(float* p, float a, float b) {
    unsigned long long gp;
    asm("cvta.to.global.u64 %0, %1;" : "=l"(gp) : "l"(p));
    asm volatile("red.global.add.v2.f32 [%0], {%1, %2};"
                 :: "l"(gp), "f"(a), "f"(b) : "memory");
}

__global__ void __launch_bounds__(256) k_gather_pool(const __half* __restrict__ Ain,
                                                     const float* __restrict__ b3,
                                                     const int* __restrict__ batch, int n) {
    int wid = (blockIdx.x * blockDim.x + threadIdx.x) >> 5;
    if (wid >= n) return;
    const int lane = threadIdx.x & 31;
    float2 acc = gather_row((const __half2*)Ain, wid, lane);
    float dv = g_dinv[wid];
    float2 bb = *(const float2*)(b3 + lane * 2);
    float ox = fmaxf(acc.x * dv + bb.x, 0.0f);
    float oy = fmaxf(acc.y * dv + bb.y, 0.0f);
    int g = batch[wid];
    red_add_v2(&g_pool[g * 64 + lane * 2], ox, oy);
    if (lane == 0) atomicAdd(&g_cnt[g], 1.0f);
}

// ---------------- classifier head ----------------
__global__ void k_classifier(const float* __restrict__ Wc1, const float* __restrict__ bc1,
                             const float* __restrict__ Wc2, const float* __restrict__ bc2,
                             float* __restrict__ out) {
    __shared__ float p[64];
    __shared__ float z[32];
    int g = blockIdx.x;
    int t = threadIdx.x;  // 32 threads
    float inv = 1.0f / fmaxf(g_cnt[g], 1.0f);
    p[t] = g_pool[g * 64 + t] * inv;
    p[t + 32] = g_pool[g * 64 + 32 + t] * inv;
    __syncwarp();
    float acc = bc1[t];
#pragma unroll
    for (int k = 0; k < 64; k++) acc += p[k] * Wc1[k * 32 + t];
    z[t] = fmaxf(acc, 0.0f);
    __syncwarp();
    if (t < 10) {
        float a = bc2[t];
#pragma unroll
        for (int k = 0; k < 32; k++) a += z[k] * Wc2[k * 10 + t];
        out[g * 10 + t] = a;
    }
}

extern "C" void kernel_launch(void* const* d_in, const int* in_sizes, int n_in,
                              void* d_out, int out_size) {
    const float* x    = (const float*)d_in[0];
    const int*   ei   = (const int*)d_in[1];
    const int*   bat  = (const int*)d_in[2];
    const float* W1   = (const float*)d_in[3];
    const float* b1   = (const float*)d_in[4];
    const float* W2   = (const float*)d_in[5];
    const float* b2   = (const float*)d_in[6];
    const float* W3   = (const float*)d_in[7];
    const float* b3   = (const float*)d_in[8];
    const float* Wc1  = (const float*)d_in[9];
    const float* bc1  = (const float*)d_in[10];
    const float* Wc2  = (const float*)d_in[11];
    const float* bc2  = (const float*)d_in[12];

    const int n = in_sizes[0] / 128;
    const int E = in_sizes[1] / 2;
    const int* src = ei;
    const int* dst = ei + E;

    __half* dA;
    float*  dB;
    cudaGetSymbolAddress((void**)&dA, g_A16);
    cudaGetSymbolAddress((void**)&dB, g_B);

    const int TB = 256;
    int gn    = (n + TB - 1) / TB;
    int gE4   = (E + 4 * TB - 1) / (4 * TB);
    int gW    = (int)(((long long)n * 32 + TB - 1) / TB);
    int gRow2 = (n + 127) / 128;
    int nb    = (n + SCAN_BLK - 1) / SCAN_BLK;

    // ---- CSR build + layer-1 GEMM (slot 4 profiled) ----
    k_hist<<<gE4, TB>>>(dst, E);                      // launch 1
    k_scan1<<<nb, 256>>>(n);                          // launch 2
    k_scan3<<<gn, TB>>>(n, E, nb);                    // launch 3
    k_gemm<128, false><<<gRow2, TB>>>(x, W1, nullptr, dA, n);  // launch 4 <- profiled
    k_sortscatter<<<gE4, TB>>>(src, dst, E);          // launch 5

    // layer 1 aggregate
    k_gather<<<gW, TB>>>(dA, dB, n);

    // layer 2
    k_gemm<64, true><<<gRow2, TB>>>(dB, W2, b1, dA, n);
    k_gather<<<gW, TB>>>(dA, dB, n);

    // layer 3 (gather fused with pooling)
    k_gemm<64, true><<<gRow2, TB>>>(dB, W3, b2, dA, n);
    k_gather_pool<<<gW, TB>>>(dA, b3, bat, n);

    // classifier
    k_classifier<<<NGRAPH, 32>>>(Wc1, bc1, Wc2, bc2, (float*)d_out);
}

// round 11
// speedup vs baseline: 1.3874x; 1.0171x over previous
#include <cuda_runtime.h>
#include <cuda_fp16.h>

#define N_HID 64
#define MAXN 100000
#define MAXE 3200000
#define NGRAPH 512
#define SCAN_BLK 1024
#define MAXPART 128

// Scratch (device globals — no allocation allowed; zero-initialized at load)
__device__ __align__(16) float  g_dinv[MAXN];
__device__ __align__(16) int    g_cnt2[MAXN];        // zero at entry (scan1 re-zeroes)
__device__ __align__(16) int    g_off[MAXN + 1];
__device__ __align__(16) int    g_cur[MAXN];         // write cursor (starts at g_off[i])
__device__ __align__(16) int    g_part[MAXPART];
__device__ __align__(16) int    g_esrc[MAXE + 8];    // sorted src indices (4B/edge)
__device__ __align__(16) __half g_A16[(size_t)MAXN * N_HID];  // A' = dinv[row]*h[row], fp16
__device__ __align__(16) __half g_X16[(size_t)MAXN * N_HID];  // activated X for next layer, fp16
__device__ __align__(16) float  g_pool[NGRAPH * N_HID];
__device__ float g_cnt[NGRAPH];

// ---------------- histogram of dst (int4 loads) ----------------
__global__ void k_hist(const int* __restrict__ dst, int E) {
    int e4 = (blockIdx.x * blockDim.x + threadIdx.x) * 4;
    if (e4 + 3 < E) {
        int4 d = *(const int4*)(dst + e4);
        atomicAdd(&g_cnt2[d.x], 1);
        atomicAdd(&g_cnt2[d.y], 1);
        atomicAdd(&g_cnt2[d.z], 1);
        atomicAdd(&g_cnt2[d.w], 1);
    } else {
        for (int e = e4; e < E; e++) atomicAdd(&g_cnt2[dst[e]], 1);
    }
}

// ---------------- block scan (reads AND re-zeroes g_cnt2; derives dinv) ----------------
__global__ void __launch_bounds__(256) k_scan1(int n) {
    __shared__ int wt[8];
    __shared__ int wtex[8];
    const int t = threadIdx.x, lane = t & 31, warp = t >> 5;
    const int base = blockIdx.x * SCAN_BLK + t * 4;
    int a0 = (base + 0 < n) ? g_cnt2[base + 0] : 0;
    int a1 = (base + 1 < n) ? g_cnt2[base + 1] : 0;
    int a2 = (base + 2 < n) ? g_cnt2[base + 2] : 0;
    int a3 = (base + 3 < n) ? g_cnt2[base + 3] : 0;
    int sum4 = a0 + a1 + a2 + a3;
    int v = sum4;
#pragma unroll
    for (int o = 1; o < 32; o <<= 1) {
        int u = __shfl_up_sync(0xFFFFFFFFu, v, o);
        if (lane >= o) v += u;
    }
    if (lane == 31) wt[warp] = v;
    __syncthreads();
    if (t == 0) {
        int run = 0;
#pragma unroll
        for (int w = 0; w < 8; w++) { wtex[w] = run; run += wt[w]; }
        g_part[blockIdx.x] = run;
    }
    __syncthreads();
    int ex = v - sum4 + wtex[warp];
    if (base + 0 < n) { g_off[base + 0] = ex;                g_dinv[base + 0] = rsqrtf((float)a0 + 1.0f); g_cnt2[base + 0] = 0; }
    if (base + 1 < n) { g_off[base + 1] = ex + a0;           g_dinv[base + 1] = rsqrtf((float)a1 + 1.0f); g_cnt2[base + 1] = 0; }
    if (base + 2 < n) { g_off[base + 2] = ex + a0 + a1;      g_dinv[base + 2] = rsqrtf((float)a2 + 1.0f); g_cnt2[base + 2] = 0; }
    if (base + 3 < n) { g_off[base + 3] = ex + a0 + a1 + a2; g_dinv[base + 3] = rsqrtf((float)a3 + 1.0f); g_cnt2[base + 3] = 0; }
}

// ---------------- scan finalize: add block prefix; g_cur = g_off; zero pool ----------------
__global__ void __launch_bounds__(256) k_scan3(int n, int E, int nb) {
    __shared__ int sp[MAXPART];
    int t = threadIdx.x;
    if (t < MAXPART) sp[t] = (t < nb) ? g_part[t] : 0;
    __syncthreads();
    if (t == 0) {
        int run = 0;
        for (int i = 0; i < nb; i++) { int c = sp[i]; sp[i] = run; run += c; }
    }
    __syncthreads();
    int i = blockIdx.x * blockDim.x + t;
    if (i < n) {
        int o = g_off[i] + sp[i >> 10];
        g_off[i] = o;
        g_cur[i] = o;
    }
    if (i == 0) g_off[n] = E;
    if (i < NGRAPH * N_HID) g_pool[i] = 0.0f;
    if (i < NGRAPH) g_cnt[i] = 0.0f;
}

// ---------------- counting-sort by dst: store ONLY src ----------------
__global__ void k_sortscatter(const int* __restrict__ src, const int* __restrict__ dst, int E) {
    int e4 = (blockIdx.x * blockDim.x + threadIdx.x) * 4;
    if (e4 + 3 < E) {
        int4 s = *(const int4*)(src + e4);
        int4 d = *(const int4*)(dst + e4);
        { int r = atomicAdd(&g_cur[d.x], 1); g_esrc[r] = s.x; }
        { int r = atomicAdd(&g_cur[d.y], 1); g_esrc[r] = s.y; }
        { int r = atomicAdd(&g_cur[d.z], 1); g_esrc[r] = s.z; }
        { int r = atomicAdd(&g_cur[d.w], 1); g_esrc[r] = s.w; }
    } else {
        for (int e = e4; e < E; e++) {
            int r = atomicAdd(&g_cur[dst[e]], 1);
            g_esrc[r] = src[e];
        }
    }
}

// ---------------- HMMA m16n8k16 wrapper ----------------
__device__ __forceinline__ void mma16816(float* c,
                                         unsigned a0, unsigned a1, unsigned a2, unsigned a3,
                                         unsigned b0, unsigned b1) {
    asm volatile(
        "mma.sync.aligned.m16n8k16.row.col.f32.f16.f16.f32 "
        "{%0,%1,%2,%3}, {%4,%5,%6,%7}, {%8,%9}, {%0,%1,%2,%3};"
        : "+f"(c[0]), "+f"(c[1]), "+f"(c[2]), "+f"(c[3])
        : "r"(a0), "r"(a1), "r"(a2), "r"(a3), "r"(b0), "r"(b1));
}

__device__ __forceinline__ void split2(float x, float y, __half2& hi, __half2& lo) {
    hi = __floats2half2_rn(x, y);
    float2 h = __half22float2(hi);
    lo = __floats2half2_rn(x - h.x, y - h.y);
}

// ---------------- GEMM1 (fp32 X, split both operands, k-chunk 16): A16 = dinv*(x@W1) ----------------
__global__ void __launch_bounds__(256) k_gemm1(const float* __restrict__ X,
                                               const float* __restrict__ W,
                                               __half* __restrict__ H, int n) {
    const int K = 128;
    __shared__ __half Xh[128][24], Xl[128][24];   // 16-k chunk, +8 pad (rows 48B)
    __shared__ __half Wh[64][24],  Wl[64][24];
    const int tid = threadIdx.x;
    const int wid = tid >> 5;
    const int lane = tid & 31;
    const int gID = lane >> 2;
    const int tig = lane & 3;
    const int row0 = blockIdx.x * 128;

    float acc[8][4] = {};

    for (int k0 = 0; k0 < K; k0 += 16) {
        __syncthreads();
        // W chunk: 16x64 / 256 = 4 per thread
        for (int i = tid; i < 16 * 64; i += 256) {
            int k = i >> 6, c = i & 63;
            float w = W[(size_t)(k0 + k) * 64 + c];
            __half hh = __float2half_rn(w);
            Wh[c][k] = hh;
            Wl[c][k] = __float2half_rn(w - __half2float(hh));
        }
        // X chunk: thread loads 8 floats (2 float4): r = tid>>1, q = (tid&1)*8
        {
            int r = tid >> 1, q = (tid & 1) * 8;
            int row = row0 + r;
            float4 xa = make_float4(0.f, 0.f, 0.f, 0.f), xb = xa;
            if (row < n) {
                xa = *(const float4*)(X + (size_t)row * K + k0 + q);
                xb = *(const float4*)(X + (size_t)row * K + k0 + q + 4);
            }
            __half2 h0, l0, h1, l1, h2, l2, h3, l3;
            split2(xa.x, xa.y, h0, l0); split2(xa.z, xa.w, h1, l1);
            split2(xb.x, xb.y, h2, l2); split2(xb.z, xb.w, h3, l3);
            *(__half2*)&Xh[r][q]     = h0; *(__half2*)&Xh[r][q + 2] = h1;
            *(__half2*)&Xh[r][q + 4] = h2; *(__half2*)&Xh[r][q + 6] = h3;
            *(__half2*)&Xl[r][q]     = l0; *(__half2*)&Xl[r][q + 2] = l1;
            *(__half2*)&Xl[r][q + 4] = l2; *(__half2*)&Xl[r][q + 6] = l3;
        }
        __syncthreads();

        const int r0 = wid * 16 + gID;
        unsigned ah0 = *(const unsigned*)&Xh[r0][tig * 2];
        unsigned ah1 = *(const unsigned*)&Xh[r0 + 8][tig * 2];
        unsigned ah2 = *(const unsigned*)&Xh[r0][tig * 2 + 8];
        unsigned ah3 = *(const unsigned*)&Xh[r0 + 8][tig * 2 + 8];
        unsigned al0 = *(const unsigned*)&Xl[r0][tig * 2];
        unsigned al1 = *(const unsigned*)&Xl[r0 + 8][tig * 2];
        unsigned al2 = *(const unsigned*)&Xl[r0][tig * 2 + 8];
        unsigned al3 = *(const unsigned*)&Xl[r0 + 8][tig * 2 + 8];
#pragma unroll
        for (int nt = 0; nt < 8; nt++) {
            int c = nt * 8 + gID;
            unsigned bh0 = *(const unsigned*)&Wh[c][tig * 2];
            unsigned bh1 = *(const unsigned*)&Wh[c][tig * 2 + 8];
            unsigned bl0 = *(const unsigned*)&Wl[c][tig * 2];
            unsigned bl1 = *(const unsigned*)&Wl[c][tig * 2 + 8];
            mma16816(acc[nt], ah0, ah1, ah2, ah3, bh0, bh1);
            mma16816(acc[nt], ah0, ah1, ah2, ah3, bl0, bl1);
            mma16816(acc[nt], al0, al1, al2, al3, bh0, bh1);
        }
    }

    const int r0 = row0 + wid * 16 + gID;
    const int r1 = r0 + 8;
    float dv0 = (r0 < n) ? g_dinv[r0] : 0.0f;
    float dv1 = (r1 < n) ? g_dinv[r1] : 0.0f;
#pragma unroll
    for (int nt = 0; nt < 8; nt++) {
        int c = nt * 8 + tig * 2;
        if (r0 < n) *(__half2*)&H[(size_t)r0 * 64 + c] = __floats2half2_rn(acc[nt][0] * dv0, acc[nt][1] * dv0);
        if (r1 < n) *(__half2*)&H[(size_t)r1 * 64 + c] = __floats2half2_rn(acc[nt][2] * dv1, acc[nt][3] * dv1);
    }
}

// ---------------- GEMM f16-X (layers 2,3): X exact fp16, W split -> 2 MMAs ----------------
__global__ void __launch_bounds__(256) k_gemm_f16(const __half* __restrict__ X,
                                                  const float* __restrict__ W,
                                                  __half* __restrict__ H, int n) {
    const int K = 64;
    __shared__ __half Xs[128][40];               // 32-k chunk, rows 80B
    __shared__ __half Wh[64][40], Wl[64][40];
    const int tid = threadIdx.x;
    const int wid = tid >> 5;
    const int lane = tid & 31;
    const int gID = lane >> 2;
    const int tig = lane & 3;
    const int row0 = blockIdx.x * 128;

    float acc[8][4] = {};

    for (int k0 = 0; k0 < K; k0 += 32) {
        __syncthreads();
        for (int i = tid; i < 32 * 64; i += 256) {
            int k = i >> 6, c = i & 63;
            float w = W[(size_t)(k0 + k) * 64 + c];
            __half hh = __float2half_rn(w);
            Wh[c][k] = hh;
            Wl[c][k] = __float2half_rn(w - __half2float(hh));
        }
        // X: thread copies 16 halves (2 uint4): r = tid>>1, seg = (tid&1)*16
        {
            int r = tid >> 1, seg = (tid & 1) * 16;
            int row = row0 + r;
            uint4 u0 = make_uint4(0, 0, 0, 0), u1 = u0;
            if (row < n) {
                u0 = *(const uint4*)(X + (size_t)row * 64 + k0 + seg);
                u1 = *(const uint4*)(X + (size_t)row * 64 + k0 + seg + 8);
            }
            *(uint4*)&Xs[r][seg]     = u0;
            *(uint4*)&Xs[r][seg + 8] = u1;
        }
        __syncthreads();

#pragma unroll
        for (int ks = 0; ks < 2; ks++) {
            const int kb = ks * 16;
            const int r0 = wid * 16 + gID;
            unsigned a0 = *(const unsigned*)&Xs[r0][kb + tig * 2];
            unsigned a1 = *(const unsigned*)&Xs[r0 + 8][kb + tig * 2];
            unsigned a2 = *(const unsigned*)&Xs[r0][kb + tig * 2 + 8];
            unsigned a3 = *(const unsigned*)&Xs[r0 + 8][kb + tig * 2 + 8];
#pragma unroll
            for (int nt = 0; nt < 8; nt++) {
                int c = nt * 8 + gID;
                unsigned bh0 = *(const unsigned*)&Wh[c][kb + tig * 2];
                unsigned bh1 = *(const unsigned*)&Wh[c][kb + tig * 2 + 8];
                unsigned bl0 = *(const unsigned*)&Wl[c][kb + tig * 2];
                unsigned bl1 = *(const unsigned*)&Wl[c][kb + tig * 2 + 8];
                mma16816(acc[nt], a0, a1, a2, a3, bh0, bh1);
                mma16816(acc[nt], a0, a1, a2, a3, bl0, bl1);
            }
        }
    }

    const int r0 = row0 + wid * 16 + gID;
    const int r1 = r0 + 8;
    float dv0 = (r0 < n) ? g_dinv[r0] : 0.0f;
    float dv1 = (r1 < n) ? g_dinv[r1] : 0.0f;
#pragma unroll
    for (int nt = 0; nt < 8; nt++) {
        int c = nt * 8 + tig * 2;
        if (r0 < n) *(__half2*)&H[(size_t)r0 * 64 + c] = __floats2half2_rn(acc[nt][0] * dv0, acc[nt][1] * dv0);
        if (r1 < n) *(__half2*)&H[(size_t)r1 * 64 + c] = __floats2half2_rn(acc[nt][2] * dv1, acc[nt][3] * dv1);
    }
}

// ---------------- gather core ----------------
__device__ __forceinline__ float2 gather_row(const __half2* A, int wid, int lane) {
    const int beg = g_off[wid];
    const int end = g_off[wid + 1];
    float2 acc = __half22float2(A[(size_t)wid * 32 + lane]);  // self term
    int j = beg;
    while ((j & 3) && j < end) {
        float2 v = __half22float2(A[(size_t)g_esrc[j] * 32 + lane]);
        acc.x += v.x; acc.y += v.y;
        j++;
    }
    for (; j + 8 <= end; j += 8) {
        int4 q0 = *(const int4*)&g_esrc[j + 0];
        int4 q1 = *(const int4*)&g_esrc[j + 4];
        float2 v0 = __half22float2(A[(size_t)q0.x * 32 + lane]);
        float2 v1 = __half22float2(A[(size_t)q0.y * 32 + lane]);
        float2 v2 = __half22float2(A[(size_t)q0.z * 32 + lane]);
        float2 v3 = __half22float2(A[(size_t)q0.w * 32 + lane]);
        float2 v4 = __half22float2(A[(size_t)q1.x * 32 + lane]);
        float2 v5 = __half22float2(A[(size_t)q1.y * 32 + lane]);
        float2 v6 = __half22float2(A[(size_t)q1.z * 32 + lane]);
        float2 v7 = __half22float2(A[(size_t)q1.w * 32 + lane]);
        acc.x += v0.x; acc.y += v0.y;
        acc.x += v1.x; acc.y += v1.y;
        acc.x += v2.x; acc.y += v2.y;
        acc.x += v3.x; acc.y += v3.y;
        acc.x += v4.x; acc.y += v4.y;
        acc.x += v5.x; acc.y += v5.y;
        acc.x += v6.x; acc.y += v6.y;
        acc.x += v7.x; acc.y += v7.y;
    }
    for (; j + 4 <= end; j += 4) {
        int4 q = *(const int4*)&g_esrc[j];
        float2 v0 = __half22float2(A[(size_t)q.x * 32 + lane]);
        float2 v1 = __half22float2(A[(size_t)q.y * 32 + lane]);
        float2 v2 = __half22float2(A[(size_t)q.z * 32 + lane]);
        float2 v3 = __half22float2(A[(size_t)q.w * 32 + lane]);
        acc.x += v0.x; acc.y += v0.y;
        acc.x += v1.x; acc.y += v1.y;
        acc.x += v2.x; acc.y += v2.y;
        acc.x += v3.x; acc.y += v3.y;
    }
    for (; j < end; j++) {
        float2 v = __half22float2(A[(size_t)g_esrc[j] * 32 + lane]);
        acc.x += v.x; acc.y += v.y;
    }
    return acc;
}

// gather + bias + relu -> fp16 activated X for next GEMM (layers 1,2)
__global__ void __launch_bounds__(256) k_gather_act(const __half* __restrict__ Ain,
                                                    const float* __restrict__ b,
                                                    __half* __restrict__ Xout, int n) {
    int wid = (blockIdx.x * blockDim.x + threadIdx.x) >> 5;
    if (wid >= n) return;
    const int lane = threadIdx.x & 31;
    float2 acc = gather_row((const __half2*)Ain, wid, lane);
    float dv = g_dinv[wid];
    float2 bb = *(const float2*)(b + lane * 2);
    float ox = fmaxf(acc.x * dv + bb.x, 0.0f);
    float oy = fmaxf(acc.y * dv + bb.y, 0.0f);
    ((__half2*)Xout)[(size_t)wid * 32 + lane] = __floats2half2_rn(ox, oy);
}

// gather fused with mean-pool accumulation (layer 3)
__device__ __forceinline__ void red_add_v2(float* p, float a, float b) {
    unsigned long long gp;
    asm("cvta.to.global.u64 %0, %1;" : "=l"(gp) : "l"(p));
    asm volatile("red.global.add.v2.f32 [%0], {%1, %2};"
                 :: "l"(gp), "f"(a), "f"(b) : "memory");
}

__global__ void __launch_bounds__(256) k_gather_pool(const __half* __restrict__ Ain,
                                                     const float* __restrict__ b3,
                                                     const int* __restrict__ batch, int n) {
    int wid = (blockIdx.x * blockDim.x + threadIdx.x) >> 5;
    if (wid >= n) return;
    const int lane = threadIdx.x & 31;
    float2 acc = gather_row((const __half2*)Ain, wid, lane);
    float dv = g_dinv[wid];
    float2 bb = *(const float2*)(b3 + lane * 2);
    float ox = fmaxf(acc.x * dv + bb.x, 0.0f);
    float oy = fmaxf(acc.y * dv + bb.y, 0.0f);
    int g = batch[wid];
    red_add_v2(&g_pool[g * 64 + lane * 2], ox, oy);
    if (lane == 0) atomicAdd(&g_cnt[g], 1.0f);
}

// ---------------- classifier head ----------------
__global__ void k_classifier(const float* __restrict__ Wc1, const float* __restrict__ bc1,
                             const float* __restrict__ Wc2, const float* __restrict__ bc2,
                             float* __restrict__ out) {
    __shared__ float p[64];
    __shared__ float z[32];
    int g = blockIdx.x;
    int t = threadIdx.x;  // 32 threads
    float inv = 1.0f / fmaxf(g_cnt[g], 1.0f);
    p[t] = g_pool[g * 64 + t] * inv;
    p[t + 32] = g_pool[g * 64 + 32 + t] * inv;
    __syncwarp();
    float acc = bc1[t];
#pragma unroll
    for (int k = 0; k < 64; k++) acc += p[k] * Wc1[k * 32 + t];
    z[t] = fmaxf(acc, 0.0f);
    __syncwarp();
    if (t < 10) {
        float a = bc2[t];
#pragma unroll
        for (int k = 0; k < 32; k++) a += z[k] * Wc2[k * 10 + t];
        out[g * 10 + t] = a;
    }
}

extern "C" void kernel_launch(void* const* d_in, const int* in_sizes, int n_in,
                              void* d_out, int out_size) {
    const float* x    = (const float*)d_in[0];
    const int*   ei   = (const int*)d_in[1];
    const int*   bat  = (const int*)d_in[2];
    const float* W1   = (const float*)d_in[3];
    const float* b1   = (const float*)d_in[4];
    const float* W2   = (const float*)d_in[5];
    const float* b2   = (const float*)d_in[6];
    const float* W3   = (const float*)d_in[7];
    const float* b3   = (const float*)d_in[8];
    const float* Wc1  = (const float*)d_in[9];
    const float* bc1  = (const float*)d_in[10];
    const float* Wc2  = (const float*)d_in[11];
    const float* bc2  = (const float*)d_in[12];

    const int n = in_sizes[0] / 128;
    const int E = in_sizes[1] / 2;
    const int* src = ei;
    const int* dst = ei + E;

    __half *dA, *dX;
    cudaGetSymbolAddress((void**)&dA, g_A16);
    cudaGetSymbolAddress((void**)&dX, g_X16);

    const int TB = 256;
    int gn    = (n + TB - 1) / TB;
    int gE4   = (E + 4 * TB - 1) / (4 * TB);
    int gW    = (int)(((long long)n * 32 + TB - 1) / TB);
    int gRow2 = (n + 127) / 128;
    int nb    = (n + SCAN_BLK - 1) / SCAN_BLK;

    // ---- CSR build + layer-1 GEMM (slot 4 profiled) ----
    k_hist<<<gE4, TB>>>(dst, E);                      // launch 1
    k_scan1<<<nb, 256>>>(n);                          // launch 2
    k_scan3<<<gn, TB>>>(n, E, nb);                    // launch 3
    k_gemm1<<<gRow2, TB>>>(x, W1, dA, n);             // launch 4 <- profiled
    k_sortscatter<<<gE4, TB>>>(src, dst, E);          // launch 5

    // layer 1 aggregate (+ bias1 + relu -> fp16 X)
    k_gather_act<<<gW, TB>>>(dA, b1, dX, n);

    // layer 2
    k_gemm_f16<<<gRow2, TB>>>(dX, W2, dA, n);
    k_gather_act<<<gW, TB>>>(dA, b2, dX, n);

    // layer 3 (gather fused with pooling)
    k_gemm_f16<<<gRow2, TB>>>(dX, W3, dA, n);
    k_gather_pool<<<gW, TB>>>(dA, b3, bat, n);

    // classifier
    k_classifier<<<NGRAPH, 32>>>(Wc1, bc1, Wc2, bc2, (float*)d_out);
}

// round 12
// speedup vs baseline: 1.4434x; 1.0404x over previous
#include <cuda_runtime.h>
#include <cuda_fp16.h>

#define N_HID 64
#define MAXN 100000
#define MAXE 3200000
#define NGRAPH 512
#define SCAN_BLK 1024
#define MAXPART 128

// Scratch (device globals — no allocation allowed; zero-initialized at load)
__device__ __align__(16) float  g_dinv[MAXN];
__device__ __align__(16) int    g_cnt2[MAXN];        // zero at entry (scan1 re-zeroes)
__device__ __align__(16) int    g_off[MAXN + 1];
__device__ __align__(16) int    g_cur[MAXN];         // write cursor (starts at g_off[i])
__device__ __align__(16) int    g_part[MAXPART];
__device__ __align__(16) int    g_esrc[MAXE + 8];    // sorted src indices (4B/edge)
__device__ __align__(16) __half g_A16[(size_t)MAXN * N_HID];  // A' = dinv[row]*h[row], fp16
__device__ __align__(16) __half g_X16[(size_t)MAXN * N_HID];  // activated X, fp16
__device__ __align__(16) float  g_pool[NGRAPH * N_HID];
__device__ float g_cnt[NGRAPH];

// ---------------- histogram of dst (int4 loads) ----------------
__global__ void k_hist(const int* __restrict__ dst, int E) {
    int e4 = (blockIdx.x * blockDim.x + threadIdx.x) * 4;
    if (e4 + 3 < E) {
        int4 d = *(const int4*)(dst + e4);
        atomicAdd(&g_cnt2[d.x], 1);
        atomicAdd(&g_cnt2[d.y], 1);
        atomicAdd(&g_cnt2[d.z], 1);
        atomicAdd(&g_cnt2[d.w], 1);
    } else {
        for (int e = e4; e < E; e++) atomicAdd(&g_cnt2[dst[e]], 1);
    }
}

// ---------------- block scan (reads AND re-zeroes g_cnt2; derives dinv) ----------------
__global__ void __launch_bounds__(256) k_scan1(int n) {
    __shared__ int wt[8];
    __shared__ int wtex[8];
    const int t = threadIdx.x, lane = t & 31, warp = t >> 5;
    const int base = blockIdx.x * SCAN_BLK + t * 4;
    int a0 = (base + 0 < n) ? g_cnt2[base + 0] : 0;
    int a1 = (base + 1 < n) ? g_cnt2[base + 1] : 0;
    int a2 = (base + 2 < n) ? g_cnt2[base + 2] : 0;
    int a3 = (base + 3 < n) ? g_cnt2[base + 3] : 0;
    int sum4 = a0 + a1 + a2 + a3;
    int v = sum4;
#pragma unroll
    for (int o = 1; o < 32; o <<= 1) {
        int u = __shfl_up_sync(0xFFFFFFFFu, v, o);
        if (lane >= o) v += u;
    }
    if (lane == 31) wt[warp] = v;
    __syncthreads();
    if (t == 0) {
        int run = 0;
#pragma unroll
        for (int w = 0; w < 8; w++) { wtex[w] = run; run += wt[w]; }
        g_part[blockIdx.x] = run;
    }
    __syncthreads();
    int ex = v - sum4 + wtex[warp];
    if (base + 0 < n) { g_off[base + 0] = ex;                g_dinv[base + 0] = rsqrtf((float)a0 + 1.0f); g_cnt2[base + 0] = 0; }
    if (base + 1 < n) { g_off[base + 1] = ex + a0;           g_dinv[base + 1] = rsqrtf((float)a1 + 1.0f); g_cnt2[base + 1] = 0; }
    if (base + 2 < n) { g_off[base + 2] = ex + a0 + a1;      g_dinv[base + 2] = rsqrtf((float)a2 + 1.0f); g_cnt2[base + 2] = 0; }
    if (base + 3 < n) { g_off[base + 3] = ex + a0 + a1 + a2; g_dinv[base + 3] = rsqrtf((float)a3 + 1.0f); g_cnt2[base + 3] = 0; }
}

// ---------------- scan finalize: add block prefix; g_cur = g_off; zero pool ----------------
__global__ void __launch_bounds__(256) k_scan3(int n, int E, int nb) {
    __shared__ int sp[MAXPART];
    int t = threadIdx.x;
    if (t < MAXPART) sp[t] = (t < nb) ? g_part[t] : 0;
    __syncthreads();
    if (t == 0) {
        int run = 0;
        for (int i = 0; i < nb; i++) { int c = sp[i]; sp[i] = run; run += c; }
    }
    __syncthreads();
    int i = blockIdx.x * blockDim.x + t;
    if (i < n) {
        int o = g_off[i] + sp[i >> 10];
        g_off[i] = o;
        g_cur[i] = o;
    }
    if (i == 0) g_off[n] = E;
    if (i < NGRAPH * N_HID) g_pool[i] = 0.0f;
    if (i < NGRAPH) g_cnt[i] = 0.0f;
}

// ---------------- counting-sort by dst: store ONLY src ----------------
__global__ void k_sortscatter(const int* __restrict__ src, const int* __restrict__ dst, int E) {
    int e4 = (blockIdx.x * blockDim.x + threadIdx.x) * 4;
    if (e4 + 3 < E) {
        int4 s = *(const int4*)(src + e4);
        int4 d = *(const int4*)(dst + e4);
        { int r = atomicAdd(&g_cur[d.x], 1); g_esrc[r] = s.x; }
        { int r = atomicAdd(&g_cur[d.y], 1); g_esrc[r] = s.y; }
        { int r = atomicAdd(&g_cur[d.z], 1); g_esrc[r] = s.z; }
        { int r = atomicAdd(&g_cur[d.w], 1); g_esrc[r] = s.w; }
    } else {
        for (int e = e4; e < E; e++) {
            int r = atomicAdd(&g_cur[dst[e]], 1);
            g_esrc[r] = src[e];
        }
    }
}

// ---------------- HMMA m16n8k16 wrapper ----------------
__device__ __forceinline__ void mma16816(float* c,
                                         unsigned a0, unsigned a1, unsigned a2, unsigned a3,
                                         unsigned b0, unsigned b1) {
    asm volatile(
        "mma.sync.aligned.m16n8k16.row.col.f32.f16.f16.f32 "
        "{%0,%1,%2,%3}, {%4,%5,%6,%7}, {%8,%9}, {%0,%1,%2,%3};"
        : "+f"(c[0]), "+f"(c[1]), "+f"(c[2]), "+f"(c[3])
        : "r"(a0), "r"(a1), "r"(a2), "r"(a3), "r"(b0), "r"(b1));
}

__device__ __forceinline__ void split2(float x, float y, __half2& hi, __half2& lo) {
    hi = __floats2half2_rn(x, y);
    float2 h = __half22float2(hi);
    lo = __floats2half2_rn(x - h.x, y - h.y);
}

// ---------------- GEMM1: fp32 X (register-double-buffered), split operands, k-chunk 32 ----------------
__global__ void __launch_bounds__(256, 3) k_gemm1(const float* __restrict__ X,
                                                  const float* __restrict__ W,
                                                  __half* __restrict__ H, int n) {
    const int K = 128;
    __shared__ __half Xh[128][40], Xl[128][40];   // 32-k chunk, +8 pad
    __shared__ __half Wh[64][40],  Wl[64][40];
    const int tid = threadIdx.x;
    const int wid = tid >> 5;
    const int lane = tid & 31;
    const int gID = lane >> 2;
    const int tig = lane & 3;
    const int row0 = blockIdx.x * 128;

    // this thread's X slice: row xr, 16 consecutive k starting at xq
    const int xr = tid >> 1;
    const int xq = (tid & 1) * 16;
    const int xrow = row0 + xr;

    float4 xv[4];
#pragma unroll
    for (int u = 0; u < 4; u++) {
        xv[u] = make_float4(0.f, 0.f, 0.f, 0.f);
        if (xrow < n) xv[u] = *(const float4*)(X + (size_t)xrow * K + xq + u * 4);
    }

    float acc[8][4] = {};

    for (int c0 = 0; c0 < 4; c0++) {
        __syncthreads();
        // W chunk from L2 (shared across all CTAs)
        const int k0 = c0 * 32;
        for (int i = tid; i < 32 * 64; i += 256) {
            int k = i >> 6, c = i & 63;
            float w = W[(size_t)(k0 + k) * 64 + c];
            __half hh = __float2half_rn(w);
            Wh[c][k] = hh;
            Wl[c][k] = __float2half_rn(w - __half2float(hh));
        }
        // X chunk from regs (split)
#pragma unroll
        for (int u = 0; u < 4; u++) {
            __half2 h0, l0, h1, l1;
            split2(xv[u].x, xv[u].y, h0, l0);
            split2(xv[u].z, xv[u].w, h1, l1);
            *(__half2*)&Xh[xr][xq + u * 4]     = h0;
            *(__half2*)&Xh[xr][xq + u * 4 + 2] = h1;
            *(__half2*)&Xl[xr][xq + u * 4]     = l0;
            *(__half2*)&Xl[xr][xq + u * 4 + 2] = l1;
        }
        __syncthreads();

        // prefetch next X chunk into regs (overlaps with MMA below)
        if (c0 < 3) {
            const int k0n = k0 + 32;
#pragma unroll
            for (int u = 0; u < 4; u++) {
                float4 t = make_float4(0.f, 0.f, 0.f, 0.f);
                if (xrow < n) t = *(const float4*)(X + (size_t)xrow * K + k0n + xq + u * 4);
                xv[u] = t;
            }
        }

#pragma unroll
        for (int ks = 0; ks < 2; ks++) {
            const int kb = ks * 16;
            const int r0 = wid * 16 + gID;
            unsigned ah0 = *(const unsigned*)&Xh[r0][kb + tig * 2];
            unsigned ah1 = *(const unsigned*)&Xh[r0 + 8][kb + tig * 2];
            unsigned ah2 = *(const unsigned*)&Xh[r0][kb + tig * 2 + 8];
            unsigned ah3 = *(const unsigned*)&Xh[r0 + 8][kb + tig * 2 + 8];
            unsigned al0 = *(const unsigned*)&Xl[r0][kb + tig * 2];
            unsigned al1 = *(const unsigned*)&Xl[r0 + 8][kb + tig * 2];
            unsigned al2 = *(const unsigned*)&Xl[r0][kb + tig * 2 + 8];
            unsigned al3 = *(const unsigned*)&Xl[r0 + 8][kb + tig * 2 + 8];
#pragma unroll
            for (int nt = 0; nt < 8; nt++) {
                int c = nt * 8 + gID;
                unsigned bh0 = *(const unsigned*)&Wh[c][kb + tig * 2];
                unsigned bh1 = *(const unsigned*)&Wh[c][kb + tig * 2 + 8];
                unsigned bl0 = *(const unsigned*)&Wl[c][kb + tig * 2];
                unsigned bl1 = *(const unsigned*)&Wl[c][kb + tig * 2 + 8];
                mma16816(acc[nt], ah0, ah1, ah2, ah3, bh0, bh1);
                mma16816(acc[nt], ah0, ah1, ah2, ah3, bl0, bl1);
                mma16816(acc[nt], al0, al1, al2, al3, bh0, bh1);
            }
        }
    }

    const int r0 = row0 + wid * 16 + gID;
    const int r1 = r0 + 8;
    float dv0 = (r0 < n) ? g_dinv[r0] : 0.0f;
    float dv1 = (r1 < n) ? g_dinv[r1] : 0.0f;
#pragma unroll
    for (int nt = 0; nt < 8; nt++) {
        int c = nt * 8 + tig * 2;
        if (r0 < n) *(__half2*)&H[(size_t)r0 * 64 + c] = __floats2half2_rn(acc[nt][0] * dv0, acc[nt][1] * dv0);
        if (r1 < n) *(__half2*)&H[(size_t)r1 * 64 + c] = __floats2half2_rn(acc[nt][2] * dv1, acc[nt][3] * dv1);
    }
}

// ---------------- GEMM f16-X (layers 2,3): X exact fp16, W split -> 2 MMAs ----------------
__global__ void __launch_bounds__(256) k_gemm_f16(const __half* __restrict__ X,
                                                  const float* __restrict__ W,
                                                  __half* __restrict__ H, int n) {
    const int K = 64;
    __shared__ __half Xs[128][40];
    __shared__ __half Wh[64][40], Wl[64][40];
    const int tid = threadIdx.x;
    const int wid = tid >> 5;
    const int lane = tid & 31;
    const int gID = lane >> 2;
    const int tig = lane & 3;
    const int row0 = blockIdx.x * 128;

    float acc[8][4] = {};

    for (int k0 = 0; k0 < K; k0 += 32) {
        __syncthreads();
        for (int i = tid; i < 32 * 64; i += 256) {
            int k = i >> 6, c = i & 63;
            float w = W[(size_t)(k0 + k) * 64 + c];
            __half hh = __float2half_rn(w);
            Wh[c][k] = hh;
            Wl[c][k] = __float2half_rn(w - __half2float(hh));
        }
        {
            int r = tid >> 1, seg = (tid & 1) * 16;
            int row = row0 + r;
            uint4 u0 = make_uint4(0, 0, 0, 0), u1 = u0;
            if (row < n) {
                u0 = *(const uint4*)(X + (size_t)row * 64 + k0 + seg);
                u1 = *(const uint4*)(X + (size_t)row * 64 + k0 + seg + 8);
            }
            *(uint4*)&Xs[r][seg]     = u0;
            *(uint4*)&Xs[r][seg + 8] = u1;
        }
        __syncthreads();

#pragma unroll
        for (int ks = 0; ks < 2; ks++) {
            const int kb = ks * 16;
            const int r0 = wid * 16 + gID;
            unsigned a0 = *(const unsigned*)&Xs[r0][kb + tig * 2];
            unsigned a1 = *(const unsigned*)&Xs[r0 + 8][kb + tig * 2];
            unsigned a2 = *(const unsigned*)&Xs[r0][kb + tig * 2 + 8];
            unsigned a3 = *(const unsigned*)&Xs[r0 + 8][kb + tig * 2 + 8];
#pragma unroll
            for (int nt = 0; nt < 8; nt++) {
                int c = nt * 8 + gID;
                unsigned bh0 = *(const unsigned*)&Wh[c][kb + tig * 2];
                unsigned bh1 = *(const unsigned*)&Wh[c][kb + tig * 2 + 8];
                unsigned bl0 = *(const unsigned*)&Wl[c][kb + tig * 2];
                unsigned bl1 = *(const unsigned*)&Wl[c][kb + tig * 2 + 8];
                mma16816(acc[nt], a0, a1, a2, a3, bh0, bh1);
                mma16816(acc[nt], a0, a1, a2, a3, bl0, bl1);
            }
        }
    }

    const int r0 = row0 + wid * 16 + gID;
    const int r1 = r0 + 8;
    float dv0 = (r0 < n) ? g_dinv[r0] : 0.0f;
    float dv1 = (r1 < n) ? g_dinv[r1] : 0.0f;
#pragma unroll
    for (int nt = 0; nt < 8; nt++) {
        int c = nt * 8 + tig * 2;
        if (r0 < n) *(__half2*)&H[(size_t)r0 * 64 + c] = __floats2half2_rn(acc[nt][0] * dv0, acc[nt][1] * dv0);
        if (r1 < n) *(__half2*)&H[(size_t)r1 * 64 + c] = __floats2half2_rn(acc[nt][2] * dv1, acc[nt][3] * dv1);
    }
}

// ---------------- gather core ----------------
__device__ __forceinline__ float2 gather_row(const __half2* A, int wid, int lane) {
    const int beg = g_off[wid];
    const int end = g_off[wid + 1];
    float2 acc = __half22float2(A[(size_t)wid * 32 + lane]);  // self term
    int j = beg;
    while ((j & 3) && j < end) {
        float2 v = __half22float2(A[(size_t)g_esrc[j] * 32 + lane]);
        acc.x += v.x; acc.y += v.y;
        j++;
    }
    for (; j + 8 <= end; j += 8) {
        int4 q0 = *(const int4*)&g_esrc[j + 0];
        int4 q1 = *(const int4*)&g_esrc[j + 4];
        float2 v0 = __half22float2(A[(size_t)q0.x * 32 + lane]);
        float2 v1 = __half22float2(A[(size_t)q0.y * 32 + lane]);
        float2 v2 = __half22float2(A[(size_t)q0.z * 32 + lane]);
        float2 v3 = __half22float2(A[(size_t)q0.w * 32 + lane]);
        float2 v4 = __half22float2(A[(size_t)q1.x * 32 + lane]);
        float2 v5 = __half22float2(A[(size_t)q1.y * 32 + lane]);
        float2 v6 = __half22float2(A[(size_t)q1.z * 32 + lane]);
        float2 v7 = __half22float2(A[(size_t)q1.w * 32 + lane]);
        acc.x += v0.x; acc.y += v0.y;
        acc.x += v1.x; acc.y += v1.y;
        acc.x += v2.x; acc.y += v2.y;
        acc.x += v3.x; acc.y += v3.y;
        acc.x += v4.x; acc.y += v4.y;
        acc.x += v5.x; acc.y += v5.y;
        acc.x += v6.x; acc.y += v6.y;
        acc.x += v7.x; acc.y += v7.y;
    }
    for (; j + 4 <= end; j += 4) {
        int4 q = *(const int4*)&g_esrc[j];
        float2 v0 = __half22float2(A[(size_t)q.x * 32 + lane]);
        float2 v1 = __half22float2(A[(size_t)q.y * 32 + lane]);
        float2 v2 = __half22float2(A[(size_t)q.z * 32 + lane]);
        float2 v3 = __half22float2(A[(size_t)q.w * 32 + lane]);
        acc.x += v0.x; acc.y += v0.y;
        acc.x += v1.x; acc.y += v1.y;
        acc.x += v2.x; acc.y += v2.y;
        acc.x += v3.x; acc.y += v3.y;
    }
    for (; j < end; j++) {
        float2 v = __half22float2(A[(size_t)g_esrc[j] * 32 + lane]);
        acc.x += v.x; acc.y += v.y;
    }
    return acc;
}

// gather + bias + relu -> fp16 activated X for next GEMM (layers 1,2)
__global__ void __launch_bounds__(256) k_gather_act(const __half* __restrict__ Ain,
                                                    const float* __restrict__ b,
                                                    __half* __restrict__ Xout, int n) {
    int wid = (blockIdx.x * blockDim.x + threadIdx.x) >> 5;
    if (wid >= n) return;
    const int lane = threadIdx.x & 31;
    float2 acc = gather_row((const __half2*)Ain, wid, lane);
    float dv = g_dinv[wid];
    float2 bb = *(const float2*)(b + lane * 2);
    float ox = fmaxf(acc.x * dv + bb.x, 0.0f);
    float oy = fmaxf(acc.y * dv + bb.y, 0.0f);
    ((__half2*)Xout)[(size_t)wid * 32 + lane] = __floats2half2_rn(ox, oy);
}

// gather fused with mean-pool accumulation (layer 3)
__device__ __forceinline__ void red_add_v2(float* p, float a, float b) {
    unsigned long long gp;
    asm("cvta.to.global.u64 %0, %1;" : "=l"(gp) : "l"(p));
    asm volatile("red.global.add.v2.f32 [%0], {%1, %2};"
                 :: "l"(gp), "f"(a), "f"(b) : "memory");
}

__global__ void __launch_bounds__(256) k_gather_pool(const __half* __restrict__ Ain,
                                                     const float* __restrict__ b3,
                                                     const int* __restrict__ batch, int n) {
    int wid = (blockIdx.x * blockDim.x + threadIdx.x) >> 5;
    if (wid >= n) return;
    const int lane = threadIdx.x & 31;
    float2 acc = gather_row((const __half2*)Ain, wid, lane);
    float dv = g_dinv[wid];
    float2 bb = *(const float2*)(b3 + lane * 2);
    float ox = fmaxf(acc.x * dv + bb.x, 0.0f);
    float oy = fmaxf(acc.y * dv + bb.y, 0.0f);
    int g = batch[wid];
    red_add_v2(&g_pool[g * 64 + lane * 2], ox, oy);
    if (lane == 0) atomicAdd(&g_cnt[g], 1.0f);
}

// ---------------- classifier head ----------------
__global__ void k_classifier(const float* __restrict__ Wc1, const float* __restrict__ bc1,
                             const float* __restrict__ Wc2, const float* __restrict__ bc2,
                             float* __restrict__ out) {
    __shared__ float p[64];
    __shared__ float z[32];
    int g = blockIdx.x;
    int t = threadIdx.x;  // 32 threads
    float inv = 1.0f / fmaxf(g_cnt[g], 1.0f);
    p[t] = g_pool[g * 64 + t] * inv;
    p[t + 32] = g_pool[g * 64 + 32 + t] * inv;
    __syncwarp();
    float acc = bc1[t];
#pragma unroll
    for (int k = 0; k < 64; k++) acc += p[k] * Wc1[k * 32 + t];
    z[t] = fmaxf(acc, 0.0f);
    __syncwarp();
    if (t < 10) {
        float a = bc2[t];
#pragma unroll
        for (int k = 0; k < 32; k++) a += z[k] * Wc2[k * 10 + t];
        out[g * 10 + t] = a;
    }
}

extern "C" void kernel_launch(void* const* d_in, const int* in_sizes, int n_in,
                              void* d_out, int out_size) {
    const float* x    = (const float*)d_in[0];
    const int*   ei   = (const int*)d_in[1];
    const int*   bat  = (const int*)d_in[2];
    const float* W1   = (const float*)d_in[3];
    const float* b1   = (const float*)d_in[4];
    const float* W2   = (const float*)d_in[5];
    const float* b2   = (const float*)d_in[6];
    const float* W3   = (const float*)d_in[7];
    const float* b3   = (const float*)d_in[8];
    const float* Wc1  = (const float*)d_in[9];
    const float* bc1  = (const float*)d_in[10];
    const float* Wc2  = (const float*)d_in[11];
    const float* bc2  = (const float*)d_in[12];

    const int n = in_sizes[0] / 128;
    const int E = in_sizes[1] / 2;
    const int* src = ei;
    const int* dst = ei + E;

    __half *dA, *dX;
    cudaGetSymbolAddress((void**)&dA, g_A16);
    cudaGetSymbolAddress((void**)&dX, g_X16);

    const int TB = 256;
    int gn    = (n + TB - 1) / TB;
    int gE4   = (E + 4 * TB - 1) / (4 * TB);
    int gW    = (int)(((long long)n * 32 + TB - 1) / TB);
    int gRow2 = (n + 127) / 128;
    int nb    = (n + SCAN_BLK - 1) / SCAN_BLK;

    // ---- CSR build + layer-1 GEMM (slot 4 profiled) ----
    k_hist<<<gE4, TB>>>(dst, E);                      // launch 1
    k_scan1<<<nb, 256>>>(n);                          // launch 2
    k_scan3<<<gn, TB>>>(n, E, nb);                    // launch 3
    k_gemm1<<<gRow2, TB>>>(x, W1, dA, n);             // launch 4 <- profiled
    k_sortscatter<<<gE4, TB>>>(src, dst, E);          // launch 5

    // layer 1 aggregate (+ bias1 + relu -> fp16 X)
    k_gather_act<<<gW, TB>>>(dA, b1, dX, n);

    // layer 2
    k_gemm_f16<<<gRow2, TB>>>(dX, W2, dA, n);
    k_gather_act<<<gW, TB>>>(dA, b2, dX, n);

    // layer 3 (gather fused with pooling)
    k_gemm_f16<<<gRow2, TB>>>(dX, W3, dA, n);
    k_gather_pool<<<gW, TB>>>(dA, b3, bat, n);

    // classifier
    k_classifier<<<NGRAPH, 32>>>(Wc1, bc1, Wc2, bc2, (float*)d_out);
}

// round 13
// speedup vs baseline: 1.4986x; 1.0382x over previous
#include <cuda_runtime.h>
#include <cuda_fp16.h>

#define N_HID 64
#define MAXN 100000
#define MAXE 3200000
#define NGRAPH 512
#define SCAN_BLK 1024
#define MAXPART 128

// Scratch (device globals — no allocation allowed; zero-initialized at load)
__device__ __align__(16) float  g_dinv[MAXN];
__device__ __align__(16) int    g_cnt2[MAXN];        // zero at entry (scan1 re-zeroes)
__device__ __align__(16) int    g_off[MAXN + 1];
__device__ __align__(16) int    g_part[MAXPART];
__device__ __align__(16) int    g_rank[MAXE + 8];    // per-edge rank within its dst bucket
__device__ __align__(16) int    g_esrc[MAXE + 8];    // sorted src indices (4B/edge)
__device__ __align__(16) __half g_A16[(size_t)MAXN * N_HID];  // A' = dinv[row]*h[row], fp16
__device__ __align__(16) __half g_X16[(size_t)MAXN * N_HID];  // activated X, fp16
__device__ __align__(16) float  g_pool[NGRAPH * N_HID];
__device__ float g_cnt[NGRAPH];

// ---------------- HMMA m16n8k16 wrapper ----------------
__device__ __forceinline__ void mma16816(float* c,
                                         unsigned a0, unsigned a1, unsigned a2, unsigned a3,
                                         unsigned b0, unsigned b1) {
    asm volatile(
        "mma.sync.aligned.m16n8k16.row.col.f32.f16.f16.f32 "
        "{%0,%1,%2,%3}, {%4,%5,%6,%7}, {%8,%9}, {%0,%1,%2,%3};"
        : "+f"(c[0]), "+f"(c[1]), "+f"(c[2]), "+f"(c[3])
        : "r"(a0), "r"(a1), "r"(a2), "r"(a3), "r"(b0), "r"(b1));
}

__device__ __forceinline__ void split2(float x, float y, __half2& hi, __half2& lo) {
    hi = __floats2half2_rn(x, y);
    float2 h = __half22float2(hi);
    lo = __floats2half2_rn(x - h.x, y - h.y);
}

// ---------------- FUSED: layer-1 GEMM (blocks < nG) + dst histogram w/ rank (rest) ----------------
__global__ void __launch_bounds__(256, 3) k_gemm1_hist(const float* __restrict__ X,
                                                       const float* __restrict__ W,
                                                       __half* __restrict__ H,
                                                       const int* __restrict__ dst,
                                                       int n, int E, int nG) {
    const int tid = threadIdx.x;
    if (blockIdx.x >= nG) {
        // ---- histogram path: rank = fetch-and-add ----
        int e4 = ((blockIdx.x - nG) * 256 + tid) * 4;
        if (e4 + 3 < E) {
            int4 d = *(const int4*)(dst + e4);
            int4 r;
            r.x = atomicAdd(&g_cnt2[d.x], 1);
            r.y = atomicAdd(&g_cnt2[d.y], 1);
            r.z = atomicAdd(&g_cnt2[d.z], 1);
            r.w = atomicAdd(&g_cnt2[d.w], 1);
            *(int4*)(g_rank + e4) = r;
        } else {
            for (int e = e4; e < E; e++) g_rank[e] = atomicAdd(&g_cnt2[dst[e]], 1);
        }
        return;
    }

    // ---- GEMM path (identical to R12 winner) ----
    const int K = 128;
    __shared__ __half Xh[128][40], Xl[128][40];
    __shared__ __half Wh[64][40],  Wl[64][40];
    const int wid = tid >> 5;
    const int lane = tid & 31;
    const int gID = lane >> 2;
    const int tig = lane & 3;
    const int row0 = blockIdx.x * 128;

    const int xr = tid >> 1;
    const int xq = (tid & 1) * 16;
    const int xrow = row0 + xr;

    float4 xv[4];
#pragma unroll
    for (int u = 0; u < 4; u++) {
        xv[u] = make_float4(0.f, 0.f, 0.f, 0.f);
        if (xrow < n) xv[u] = *(const float4*)(X + (size_t)xrow * K + xq + u * 4);
    }

    float acc[8][4] = {};

    for (int c0 = 0; c0 < 4; c0++) {
        __syncthreads();
        const int k0 = c0 * 32;
        for (int i = tid; i < 32 * 64; i += 256) {
            int k = i >> 6, c = i & 63;
            float w = W[(size_t)(k0 + k) * 64 + c];
            __half hh = __float2half_rn(w);
            Wh[c][k] = hh;
            Wl[c][k] = __float2half_rn(w - __half2float(hh));
        }
#pragma unroll
        for (int u = 0; u < 4; u++) {
            __half2 h0, l0, h1, l1;
            split2(xv[u].x, xv[u].y, h0, l0);
            split2(xv[u].z, xv[u].w, h1, l1);
            *(__half2*)&Xh[xr][xq + u * 4]     = h0;
            *(__half2*)&Xh[xr][xq + u * 4 + 2] = h1;
            *(__half2*)&Xl[xr][xq + u * 4]     = l0;
            *(__half2*)&Xl[xr][xq + u * 4 + 2] = l1;
        }
        __syncthreads();

        if (c0 < 3) {
            const int k0n = k0 + 32;
#pragma unroll
            for (int u = 0; u < 4; u++) {
                float4 t = make_float4(0.f, 0.f, 0.f, 0.f);
                if (xrow < n) t = *(const float4*)(X + (size_t)xrow * K + k0n + xq + u * 4);
                xv[u] = t;
            }
        }

#pragma unroll
        for (int ks = 0; ks < 2; ks++) {
            const int kb = ks * 16;
            const int r0 = wid * 16 + gID;
            unsigned ah0 = *(const unsigned*)&Xh[r0][kb + tig * 2];
            unsigned ah1 = *(const unsigned*)&Xh[r0 + 8][kb + tig * 2];
            unsigned ah2 = *(const unsigned*)&Xh[r0][kb + tig * 2 + 8];
            unsigned ah3 = *(const unsigned*)&Xh[r0 + 8][kb + tig * 2 + 8];
            unsigned al0 = *(const unsigned*)&Xl[r0][kb + tig * 2];
            unsigned al1 = *(const unsigned*)&Xl[r0 + 8][kb + tig * 2];
            unsigned al2 = *(const unsigned*)&Xl[r0][kb + tig * 2 + 8];
            unsigned al3 = *(const unsigned*)&Xl[r0 + 8][kb + tig * 2 + 8];
#pragma unroll
            for (int nt = 0; nt < 8; nt++) {
                int c = nt * 8 + gID;
                unsigned bh0 = *(const unsigned*)&Wh[c][kb + tig * 2];
                unsigned bh1 = *(const unsigned*)&Wh[c][kb + tig * 2 + 8];
                unsigned bl0 = *(const unsigned*)&Wl[c][kb + tig * 2];
                unsigned bl1 = *(const unsigned*)&Wl[c][kb + tig * 2 + 8];
                mma16816(acc[nt], ah0, ah1, ah2, ah3, bh0, bh1);
                mma16816(acc[nt], ah0, ah1, ah2, ah3, bl0, bl1);
                mma16816(acc[nt], al0, al1, al2, al3, bh0, bh1);
            }
        }
    }

    // NOTE: dinv is not ready yet (hist runs concurrently) -> store UNSCALED h.
    // The dinv scaling moves into the gather's self-term and edge reads?? No —
    // instead we apply dinv in a tiny epilogue pass fused into k_scan3b (see below).
    const int r0 = row0 + wid * 16 + gID;
    const int r1 = r0 + 8;
#pragma unroll
    for (int nt = 0; nt < 8; nt++) {
        int c = nt * 8 + tig * 2;
        if (r0 < n) *(__half2*)&H[(size_t)r0 * 64 + c] = __floats2half2_rn(acc[nt][0], acc[nt][1]);
        if (r1 < n) *(__half2*)&H[(size_t)r1 * 64 + c] = __floats2half2_rn(acc[nt][2], acc[nt][3]);
    }
}

// ---------------- block scan (reads AND re-zeroes g_cnt2; derives dinv) ----------------
__global__ void __launch_bounds__(256) k_scan1(int n) {
    __shared__ int wt[8];
    __shared__ int wtex[8];
    const int t = threadIdx.x, lane = t & 31, warp = t >> 5;
    const int base = blockIdx.x * SCAN_BLK + t * 4;
    int a0 = (base + 0 < n) ? g_cnt2[base + 0] : 0;
    int a1 = (base + 1 < n) ? g_cnt2[base + 1] : 0;
    int a2 = (base + 2 < n) ? g_cnt2[base + 2] : 0;
    int a3 = (base + 3 < n) ? g_cnt2[base + 3] : 0;
    int sum4 = a0 + a1 + a2 + a3;
    int v = sum4;
#pragma unroll
    for (int o = 1; o < 32; o <<= 1) {
        int u = __shfl_up_sync(0xFFFFFFFFu, v, o);
        if (lane >= o) v += u;
    }
    if (lane == 31) wt[warp] = v;
    __syncthreads();
    if (t == 0) {
        int run = 0;
#pragma unroll
        for (int w = 0; w < 8; w++) { wtex[w] = run; run += wt[w]; }
        g_part[blockIdx.x] = run;
    }
    __syncthreads();
    int ex = v - sum4 + wtex[warp];
    if (base + 0 < n) { g_off[base + 0] = ex;                g_dinv[base + 0] = rsqrtf((float)a0 + 1.0f); g_cnt2[base + 0] = 0; }
    if (base + 1 < n) { g_off[base + 1] = ex + a0;           g_dinv[base + 1] = rsqrtf((float)a1 + 1.0f); g_cnt2[base + 1] = 0; }
    if (base + 2 < n) { g_off[base + 2] = ex + a0 + a1;      g_dinv[base + 2] = rsqrtf((float)a2 + 1.0f); g_cnt2[base + 2] = 0; }
    if (base + 3 < n) { g_off[base + 3] = ex + a0 + a1 + a2; g_dinv[base + 3] = rsqrtf((float)a3 + 1.0f); g_cnt2[base + 3] = 0; }
}

// ---------------- scan finalize + deferred dinv scaling of A16 + pool zero ----------------
__global__ void __launch_bounds__(256) k_scan3(int n, int E, int nb, __half* __restrict__ H) {
    __shared__ int sp[MAXPART];
    int t = threadIdx.x;
    if (t < MAXPART) sp[t] = (t < nb) ? g_part[t] : 0;
    __syncthreads();
    if (t == 0) {
        int run = 0;
        for (int i = 0; i < nb; i++) { int c = sp[i]; sp[i] = run; run += c; }
    }
    __syncthreads();
    int i = blockIdx.x * blockDim.x + t;
    if (i < n) g_off[i] += sp[i >> 10];
    if (i == 0) g_off[n] = E;
    if (i < NGRAPH * N_HID) g_pool[i] = 0.0f;
    if (i < NGRAPH) g_cnt[i] = 0.0f;
    // scale A16 rows by dinv (deferred from fused gemm1): 8 rows per block beyond scan work
    // grid covers n*? -> separate index space: each thread scales 8 half2 of one row chunk
    long long idx = (long long)blockIdx.x * blockDim.x + t;
    long long total = (long long)n * 8;   // 8 threads per row, each does 4 half2 (32B)
    if (idx < total) {
        int row = (int)(idx >> 3);
        int seg = (int)(idx & 7) * 4;     // half2 offset
        float dv = g_dinv[row];
        __half2 dv2 = __floats2half2_rn(dv, dv);
        __half2* p = (__half2*)H + (size_t)row * 32 + seg;
        uint2 u = *(uint2*)p;
        __half2* hp = (__half2*)&u;
        hp[0] = __hmul2(hp[0], dv2);
        hp[1] = __hmul2(hp[1], dv2);
        uint2 u2 = *((uint2*)p + 1);
        __half2* hp2 = (__half2*)&u2;
        hp2[0] = __hmul2(hp2[0], dv2);
        hp2[1] = __hmul2(hp2[1], dv2);
        *(uint2*)p = u;
        *((uint2*)p + 1) = u2;
    }
}

// ---------------- counting-sort by dst using precomputed rank (no atomics) ----------------
__global__ void k_sortscatter(const int* __restrict__ src, const int* __restrict__ dst, int E) {
    int e4 = (blockIdx.x * blockDim.x + threadIdx.x) * 4;
    if (e4 + 3 < E) {
        int4 s = *(const int4*)(src + e4);
        int4 d = *(const int4*)(dst + e4);
        int4 r = *(const int4*)(g_rank + e4);
        g_esrc[g_off[d.x] + r.x] = s.x;
        g_esrc[g_off[d.y] + r.y] = s.y;
        g_esrc[g_off[d.z] + r.z] = s.z;
        g_esrc[g_off[d.w] + r.w] = s.w;
    } else {
        for (int e = e4; e < E; e++)
            g_esrc[g_off[dst[e]] + g_rank[e]] = src[e];
    }
}

// ---------------- GEMM f16-X (layers 2,3): X exact fp16, W split -> 2 MMAs ----------------
__global__ void __launch_bounds__(256) k_gemm_f16(const __half* __restrict__ X,
                                                  const float* __restrict__ W,
                                                  __half* __restrict__ H, int n) {
    const int K = 64;
    __shared__ __half Xs[128][40];
    __shared__ __half Wh[64][40], Wl[64][40];
    const int tid = threadIdx.x;
    const int wid = tid >> 5;
    const int lane = tid & 31;
    const int gID = lane >> 2;
    const int tig = lane & 3;
    const int row0 = blockIdx.x * 128;

    float acc[8][4] = {};

    for (int k0 = 0; k0 < K; k0 += 32) {
        __syncthreads();
        for (int i = tid; i < 32 * 64; i += 256) {
            int k = i >> 6, c = i & 63;
            float w = W[(size_t)(k0 + k) * 64 + c];
            __half hh = __float2half_rn(w);
            Wh[c][k] = hh;
            Wl[c][k] = __float2half_rn(w - __half2float(hh));
        }
        {
            int r = tid >> 1, seg = (tid & 1) * 16;
            int row = row0 + r;
            uint4 u0 = make_uint4(0, 0, 0, 0), u1 = u0;
            if (row < n) {
                u0 = *(const uint4*)(X + (size_t)row * 64 + k0 + seg);
                u1 = *(const uint4*)(X + (size_t)row * 64 + k0 + seg + 8);
            }
            *(uint4*)&Xs[r][seg]     = u0;
            *(uint4*)&Xs[r][seg + 8] = u1;
        }
        __syncthreads();

#pragma unroll
        for (int ks = 0; ks < 2; ks++) {
            const int kb = ks * 16;
            const int r0 = wid * 16 + gID;
            unsigned a0 = *(const unsigned*)&Xs[r0][kb + tig * 2];
            unsigned a1 = *(const unsigned*)&Xs[r0 + 8][kb + tig * 2];
            unsigned a2 = *(const unsigned*)&Xs[r0][kb + tig * 2 + 8];
            unsigned a3 = *(const unsigned*)&Xs[r0 + 8][kb + tig * 2 + 8];
#pragma unroll
            for (int nt = 0; nt < 8; nt++) {
                int c = nt * 8 + gID;
                unsigned bh0 = *(const unsigned*)&Wh[c][kb + tig * 2];
                unsigned bh1 = *(const unsigned*)&Wh[c][kb + tig * 2 + 8];
                unsigned bl0 = *(const unsigned*)&Wl[c][kb + tig * 2];
                unsigned bl1 = *(const unsigned*)&Wl[c][kb + tig * 2 + 8];
                mma16816(acc[nt], a0, a1, a2, a3, bh0, bh1);
                mma16816(acc[nt], a0, a1, a2, a3, bl0, bl1);
            }
        }
    }

    const int r0 = row0 + wid * 16 + gID;
    const int r1 = r0 + 8;
    float dv0 = (r0 < n) ? g_dinv[r0] : 0.0f;
    float dv1 = (r1 < n) ? g_dinv[r1] : 0.0f;
#pragma unroll
    for (int nt = 0; nt < 8; nt++) {
        int c = nt * 8 + tig * 2;
        if (r0 < n) *(__half2*)&H[(size_t)r0 * 64 + c] = __floats2half2_rn(acc[nt][0] * dv0, acc[nt][1] * dv0);
        if (r1 < n) *(__half2*)&H[(size_t)r1 * 64 + c] = __floats2half2_rn(acc[nt][2] * dv1, acc[nt][3] * dv1);
    }
}

// ---------------- gather core ----------------
__device__ __forceinline__ float2 gather_row(const __half2* A, int wid, int lane) {
    const int beg = g_off[wid];
    const int end = g_off[wid + 1];
    float2 acc = __half22float2(A[(size_t)wid * 32 + lane]);  // self term
    int j = beg;
    while ((j & 3) && j < end) {
        float2 v = __half22float2(A[(size_t)g_esrc[j] * 32 + lane]);
        acc.x += v.x; acc.y += v.y;
        j++;
    }
    for (; j + 8 <= end; j += 8) {
        int4 q0 = *(const int4*)&g_esrc[j + 0];
        int4 q1 = *(const int4*)&g_esrc[j + 4];
        float2 v0 = __half22float2(A[(size_t)q0.x * 32 + lane]);
        float2 v1 = __half22float2(A[(size_t)q0.y * 32 + lane]);
        float2 v2 = __half22float2(A[(size_t)q0.z * 32 + lane]);
        float2 v3 = __half22float2(A[(size_t)q0.w * 32 + lane]);
        float2 v4 = __half22float2(A[(size_t)q1.x * 32 + lane]);
        float2 v5 = __half22float2(A[(size_t)q1.y * 32 + lane]);
        float2 v6 = __half22float2(A[(size_t)q1.z * 32 + lane]);
        float2 v7 = __half22float2(A[(size_t)q1.w * 32 + lane]);
        acc.x += v0.x; acc.y += v0.y;
        acc.x += v1.x; acc.y += v1.y;
        acc.x += v2.x; acc.y += v2.y;
        acc.x += v3.x; acc.y += v3.y;
        acc.x += v4.x; acc.y += v4.y;
        acc.x += v5.x; acc.y += v5.y;
        acc.x += v6.x; acc.y += v6.y;
        acc.x += v7.x; acc.y += v7.y;
    }
    for (; j + 4 <= end; j += 4) {
        int4 q = *(const int4*)&g_esrc[j];
        float2 v0 = __half22float2(A[(size_t)q.x * 32 + lane]);
        float2 v1 = __half22float2(A[(size_t)q.y * 32 + lane]);
        float2 v2 = __half22float2(A[(size_t)q.z * 32 + lane]);
        float2 v3 = __half22float2(A[(size_t)q.w * 32 + lane]);
        acc.x += v0.x; acc.y += v0.y;
        acc.x += v1.x; acc.y += v1.y;
        acc.x += v2.x; acc.y += v2.y;
        acc.x += v3.x; acc.y += v3.y;
    }
    for (; j < end; j++) {
        float2 v = __half22float2(A[(size_t)g_esrc[j] * 32 + lane]);
        acc.x += v.x; acc.y += v.y;
    }
    return acc;
}

// gather + bias + relu -> fp16 activated X for next GEMM (layers 1,2)
__global__ void __launch_bounds__(256) k_gather_act(const __half* __restrict__ Ain,
                                                    const float* __restrict__ b,
                                                    __half* __restrict__ Xout, int n) {
    int wid = (blockIdx.x * blockDim.x + threadIdx.x) >> 5;
    if (wid >= n) return;
    const int lane = threadIdx.x & 31;
    float2 acc = gather_row((const __half2*)Ain, wid, lane);
    float dv = g_dinv[wid];
    float2 bb = *(const float2*)(b + lane * 2);
    float ox = fmaxf(acc.x * dv + bb.x, 0.0f);
    float oy = fmaxf(acc.y * dv + bb.y, 0.0f);
    ((__half2*)Xout)[(size_t)wid * 32 + lane] = __floats2half2_rn(ox, oy);
}

// gather fused with mean-pool accumulation (layer 3)
__device__ __forceinline__ void red_add_v2(float* p, float a, float b) {
    unsigned long long gp;
    asm("cvta.to.global.u64 %0, %1;" : "=l"(gp) : "l"(p));
    asm volatile("red.global.add.v2.f32 [%0], {%1, %2};"
                 :: "l"(gp), "f"(a), "f"(b) : "memory");
}

__global__ void __launch_bounds__(256) k_gather_pool(const __half* __restrict__ Ain,
                                                     const float* __restrict__ b3,
                                                     const int* __restrict__ batch, int n) {
    int wid = (blockIdx.x * blockDim.x + threadIdx.x) >> 5;
    if (wid >= n) return;
    const int lane = threadIdx.x & 31;
    float2 acc = gather_row((const __half2*)Ain, wid, lane);
    float dv = g_dinv[wid];
    float2 bb = *(const float2*)(b3 + lane * 2);
    float ox = fmaxf(acc.x * dv + bb.x, 0.0f);
    float oy = fmaxf(acc.y * dv + bb.y, 0.0f);
    int g = batch[wid];
    red_add_v2(&g_pool[g * 64 + lane * 2], ox, oy);
    if (lane == 0) atomicAdd(&g_cnt[g], 1.0f);
}

// ---------------- classifier head ----------------
__global__ void k_classifier(const float* __restrict__ Wc1, const float* __restrict__ bc1,
                             const float* __restrict__ Wc2, const float* __restrict__ bc2,
                             float* __restrict__ out) {
    __shared__ float p[64];
    __shared__ float z[32];
    int g = blockIdx.x;
    int t = threadIdx.x;  // 32 threads
    float inv = 1.0f / fmaxf(g_cnt[g], 1.0f);
    p[t] = g_pool[g * 64 + t] * inv;
    p[t + 32] = g_pool[g * 64 + 32 + t] * inv;
    __syncwarp();
    float acc = bc1[t];
#pragma unroll
    for (int k = 0; k < 64; k++) acc += p[k] * Wc1[k * 32 + t];
    z[t] = fmaxf(acc, 0.0f);
    __syncwarp();
    if (t < 10) {
        float a = bc2[t];
#pragma unroll
        for (int k = 0; k < 32; k++) a += z[k] * Wc2[k * 10 + t];
        out[g * 10 + t] = a;
    }
}

extern "C" void kernel_launch(void* const* d_in, const int* in_sizes, int n_in,
                              void* d_out, int out_size) {
    const float* x    = (const float*)d_in[0];
    const int*   ei   = (const int*)d_in[1];
    const int*   bat  = (const int*)d_in[2];
    const float* W1   = (const float*)d_in[3];
    const float* b1   = (const float*)d_in[4];
    const float* W2   = (const float*)d_in[5];
    const float* b2   = (const float*)d_in[6];
    const float* W3   = (const float*)d_in[7];
    const float* b3   = (const float*)d_in[8];
    const float* Wc1  = (const float*)d_in[9];
    const float* bc1  = (const float*)d_in[10];
    const float* Wc2  = (const float*)d_in[11];
    const float* bc2  = (const float*)d_in[12];

    const int n = in_sizes[0] / 128;
    const int E = in_sizes[1] / 2;
    const int* src = ei;
    const int* dst = ei + E;

    __half *dA, *dX;
    cudaGetSymbolAddress((void**)&dA, g_A16);
    cudaGetSymbolAddress((void**)&dX, g_X16);

    const int TB = 256;
    int gE4   = (E + 4 * TB - 1) / (4 * TB);
    int gW    = (int)(((long long)n * 32 + TB - 1) / TB);
    int gRow2 = (n + 127) / 128;
    int nb    = (n + SCAN_BLK - 1) / SCAN_BLK;
    // scan3 grid must cover max(n, NGRAPH*N_HID, n*8) threads
    long long s3work = (long long)n * 8;
    if (s3work < NGRAPH * N_HID) s3work = NGRAPH * N_HID;
    int gS3 = (int)((s3work + TB - 1) / TB);

    // ---- fused gemm1+hist, then scans, then rank-based sortscatter (slot 4 profiled) ----
    k_gemm1_hist<<<gRow2 + gE4, TB>>>(x, W1, dA, dst, n, E, gRow2);  // launch 1
    k_scan1<<<nb, 256>>>(n);                                          // launch 2
    k_scan3<<<gS3, TB>>>(n, E, nb, dA);                               // launch 3 (scales A16 by dinv)
    k_sortscatter<<<gE4, TB>>>(src, dst, E);                          // launch 4 <- profiled

    // layer 1 aggregate (+ bias1 + relu -> fp16 X)
    k_gather_act<<<gW, TB>>>(dA, b1, dX, n);

    // layer 2
    k_gemm_f16<<<gRow2, TB>>>(dX, W2, dA, n);
    k_gather_act<<<gW, TB>>>(dA, b2, dX, n);

    // layer 3 (gather fused with pooling)
    k_gemm_f16<<<gRow2, TB>>>(dX, W3, dA, n);
    k_gather_pool<<<gW, TB>>>(dA, b3, bat, n);

    // classifier
    k_classifier<<<NGRAPH, 32>>>(Wc1, bc1, Wc2, bc2, (float*)d_out);
}